// round 14
// baseline (speedup 1.0000x reference)
#include <cuda_runtime.h>
#include <cuda_bf16.h>
#include <cstdint>
#include <math_constants.h>

// ---------------------------------------------------------------------------
// AdaptiveAttention: B=2, S=2048, HS=1024, NH=16, HD=64, NP=8
// Round 14: R11 pipeline (ldmatrix + fused softmax) at 512 threads/CTA
//           (16 warps/SM; warp tiles 32x32 gemm/scores, 32x16 context).
// ---------------------------------------------------------------------------

constexpr int cB = 2, cS = 2048, cHS = 1024, cNH = 16, cNP = 8, cHD = 64;
constexpr float cSCALE = 0.125f;
constexpr long OUT_ELEMS  = (long)cB * cS * cHS;
constexpr long ATTN_ELEMS = (long)cB * cNH * cS * cS;

__device__ float g_Q[(long)cB * cNH * cS * cHD];
__device__ float g_K[(long)cB * cNH * cS * cHD];
__device__ float g_V[(long)cB * cNH * cS * cHD];     // [b,h,s,d]
__device__ float g_ctx[(long)cB * cS * cHS];
__device__ float g_pat[cB * cNH];
__device__ float g_WT[4L * cHS * cHS];
__device__ float g_qpart[32 * cHS];
__device__ float2 g_pstats[(long)cB * cNH * cS * 16];
__device__ float2 g_rowstats[(long)cB * cNH * cS];
__device__ float g_attn_fallback[ATTN_ELEMS];

// ---------------------------------------------------------------------------
__device__ __forceinline__ uint32_t smem_u32(const void* p) {
    uint32_t a;
    asm("{ .reg .u64 t; cvta.to.shared.u64 t, %1; cvt.u32.u64 %0, t; }" : "=r"(a) : "l"(p));
    return a;
}
__device__ __forceinline__ void mma_bf16(float c[4], const uint32_t a[4], const uint32_t b[2]) {
    asm volatile(
        "mma.sync.aligned.m16n8k16.row.col.f32.bf16.bf16.f32 "
        "{%0,%1,%2,%3}, {%4,%5,%6,%7}, {%8,%9}, {%0,%1,%2,%3};"
        : "+f"(c[0]), "+f"(c[1]), "+f"(c[2]), "+f"(c[3])
        : "r"(a[0]), "r"(a[1]), "r"(a[2]), "r"(a[3]), "r"(b[0]), "r"(b[1]));
}
__device__ __forceinline__ void ldsm_x4(uint32_t& r0, uint32_t& r1, uint32_t& r2, uint32_t& r3,
                                        uint32_t addr) {
    asm volatile("ldmatrix.sync.aligned.m8n8.x4.shared.b16 {%0,%1,%2,%3}, [%4];"
                 : "=r"(r0), "=r"(r1), "=r"(r2), "=r"(r3) : "r"(addr));
}
__device__ __forceinline__ uint32_t pk2(__nv_bfloat16 a, __nv_bfloat16 b) {
    __nv_bfloat162 t;
    t.x = a; t.y = b;
    return *(uint32_t*)&t;
}
__device__ __forceinline__ void split4_pk(float4 v, uint2& hp, uint2& lp) {
    __nv_bfloat16 h0 = __float2bfloat16_rn(v.x);
    __nv_bfloat16 h1 = __float2bfloat16_rn(v.y);
    __nv_bfloat16 h2 = __float2bfloat16_rn(v.z);
    __nv_bfloat16 h3 = __float2bfloat16_rn(v.w);
    __nv_bfloat16 l0 = __float2bfloat16_rn(v.x - __bfloat162float(h0));
    __nv_bfloat16 l1 = __float2bfloat16_rn(v.y - __bfloat162float(h1));
    __nv_bfloat16 l2 = __float2bfloat16_rn(v.z - __bfloat162float(h2));
    __nv_bfloat16 l3 = __float2bfloat16_rn(v.w - __bfloat162float(h3));
    hp.x = pk2(h0, h1); hp.y = pk2(h2, h3);
    lp.x = pk2(l0, l1); lp.y = pk2(l2, l3);
}
__device__ __forceinline__ void split1(float x, __nv_bfloat16& h, __nv_bfloat16& l) {
    h = __float2bfloat16_rn(x);
    l = __float2bfloat16_rn(x - __bfloat162float(h));
}
__device__ __forceinline__ uint32_t ldsmA_off(int lane, int rowbytes) {
    int row = (lane & 7) + (((lane >> 3) & 1) << 3);
    int k8  = (lane >> 4) & 1;
    return (uint32_t)(row * rowbytes + k8 * 16);
}
__device__ __forceinline__ uint32_t ldsmB_off(int lane, int rowbytes) {
    int row = (lane & 7) + (((lane >> 4) & 1) << 3);
    int k8  = (lane >> 3) & 1;
    return (uint32_t)(row * rowbytes + k8 * 16);
}

// ===========================================================================
// gemm_bf: 512 threads, block 128x128, K-chunk 32, warps 4(m) x 4(n),
// warp tile 32x32. ldmatrix loads. MODE 1: merged QKV scatter. MODE 0: plain.
// ===========================================================================
template <int MODE>
__global__ __launch_bounds__(512)
void gemm_bf(const float* __restrict__ A0, const float* __restrict__ A1,
             const float* __restrict__ A2, const float* __restrict__ WT,
             const float* __restrict__ b0v, const float* __restrict__ b1v,
             const float* __restrict__ b2v,
             float* __restrict__ C0, float* __restrict__ C1, float* __restrict__ C2)
{
    extern __shared__ char smraw[];
    __nv_bfloat16* Ah = (__nv_bfloat16*)smraw;        // [2][128*40]
    const int z = (MODE == 1) ? blockIdx.z : 0;
    const float* A    = z == 0 ? A0 : (z == 1 ? A1 : A2);
    const float* Bt   = WT + (size_t)z * cHS * cHS;
    const float* bias = z == 0 ? b0v : (z == 1 ? b1v : b2v);
    float* C          = z == 0 ? C0 : (z == 1 ? C1 : C2);

    const int t = threadIdx.x, lane = t & 31, wid = t >> 5;
    const int wm = wid >> 2, wn = wid & 3;
    const int gid = lane >> 2, tig = lane & 3;
    const int m0 = blockIdx.y * 128, n0 = blockIdx.x * 128;

    const uint32_t uAh = smem_u32(Ah);
    const uint32_t uAl = uAh + 2 * 5120 * 2;
    const uint32_t uBh = uAh + 4 * 5120 * 2;
    const uint32_t uBl = uAh + 6 * 5120 * 2;
    const uint32_t laneA = ldsmA_off(lane, 80) + (uint32_t)(wm * 32 * 80);
    const uint32_t laneB = ldsmB_off(lane, 80) + (uint32_t)(wn * 32 * 80);

    float c[2][4][4] = {};
    float4 rA[2], rB[2];

#pragma unroll
    for (int i = 0; i < 2; i++) {
        int idx = t + i * 512, r = idx >> 3, kq = idx & 7;
        rA[i] = *(const float4*)&A[(size_t)(m0 + r) * 1024 + kq * 4];
        rB[i] = *(const float4*)&Bt[(size_t)(n0 + r) * 1024 + kq * 4];
    }
    {
        __nv_bfloat16* Al = Ah + 2 * 5120;
        __nv_bfloat16* Bh = Ah + 4 * 5120;
        __nv_bfloat16* Bl = Ah + 6 * 5120;
#pragma unroll
        for (int i = 0; i < 2; i++) {
            int idx = t + i * 512, r = idx >> 3, kq = idx & 7;
            uint2 hp, lp;
            split4_pk(rA[i], hp, lp);
            *(uint2*)&Ah[r * 40 + kq * 4] = hp;
            *(uint2*)&Al[r * 40 + kq * 4] = lp;
            split4_pk(rB[i], hp, lp);
            *(uint2*)&Bh[r * 40 + kq * 4] = hp;
            *(uint2*)&Bl[r * 40 + kq * 4] = lp;
        }
    }
    __syncthreads();

    const int T = 32;
    for (int ch = 0; ch < T; ch++) {
        const int cur = ch & 1;
        if (ch + 1 < T) {
#pragma unroll
            for (int i = 0; i < 2; i++) {
                int idx = t + i * 512, r = idx >> 3, kq = idx & 7;
                rA[i] = *(const float4*)&A[(size_t)(m0 + r) * 1024 + (ch + 1) * 32 + kq * 4];
                rB[i] = *(const float4*)&Bt[(size_t)(n0 + r) * 1024 + (ch + 1) * 32 + kq * 4];
            }
        }
        const uint32_t bufo = (uint32_t)cur * 10240;
#pragma unroll
        for (int kk = 0; kk < 2; kk++) {
            uint32_t ah[2][4], al[2][4], bh[4][2], bl[4][2];
            const uint32_t ko = (uint32_t)kk * 32;
#pragma unroll
            for (int mi = 0; mi < 2; mi++) {
                uint32_t ao = bufo + laneA + (uint32_t)(mi * 16 * 80) + ko;
                ldsm_x4(ah[mi][0], ah[mi][1], ah[mi][2], ah[mi][3], uAh + ao);
                ldsm_x4(al[mi][0], al[mi][1], al[mi][2], al[mi][3], uAl + ao);
            }
#pragma unroll
            for (int p = 0; p < 2; p++) {
                uint32_t bo = bufo + laneB + (uint32_t)(p * 16 * 80) + ko;
                ldsm_x4(bh[2*p][0], bh[2*p][1], bh[2*p+1][0], bh[2*p+1][1], uBh + bo);
                ldsm_x4(bl[2*p][0], bl[2*p][1], bl[2*p+1][0], bl[2*p+1][1], uBl + bo);
            }
#pragma unroll
            for (int mi = 0; mi < 2; mi++)
#pragma unroll
                for (int ni = 0; ni < 4; ni++) {
                    mma_bf16(c[mi][ni], al[mi], bh[ni]);
                    mma_bf16(c[mi][ni], ah[mi], bl[ni]);
                    mma_bf16(c[mi][ni], ah[mi], bh[ni]);
                }
        }
        if (ch + 1 < T) {
            __syncthreads();
            __nv_bfloat16* Ahw = Ah + (cur ^ 1) * 5120;
            __nv_bfloat16* Alw = Ah + 2 * 5120 + (cur ^ 1) * 5120;
            __nv_bfloat16* Bhw = Ah + 4 * 5120 + (cur ^ 1) * 5120;
            __nv_bfloat16* Blw = Ah + 6 * 5120 + (cur ^ 1) * 5120;
#pragma unroll
            for (int i = 0; i < 2; i++) {
                int idx = t + i * 512, r = idx >> 3, kq = idx & 7;
                uint2 hp, lp;
                split4_pk(rA[i], hp, lp);
                *(uint2*)&Ahw[r * 40 + kq * 4] = hp;
                *(uint2*)&Alw[r * 40 + kq * 4] = lp;
                split4_pk(rB[i], hp, lp);
                *(uint2*)&Bhw[r * 40 + kq * 4] = hp;
                *(uint2*)&Blw[r * 40 + kq * 4] = lp;
            }
            __syncthreads();
        }
    }

#pragma unroll
    for (int mi = 0; mi < 2; mi++)
#pragma unroll
        for (int half = 0; half < 2; half++) {
            int m = m0 + wm * 32 + mi * 16 + gid + half * 8;
            int b = m >> 11, s = m & 2047;
#pragma unroll
            for (int ni = 0; ni < 4; ni++) {
                int n = n0 + wn * 32 + ni * 8 + tig * 2;
                float2 v;
                v.x = c[mi][ni][half * 2 + 0] + bias[n];
                v.y = c[mi][ni][half * 2 + 1] + bias[n + 1];
                if (MODE == 0) {
                    *(float2*)&C[(size_t)m * 1024 + n] = v;
                } else {
                    int h = n >> 6, d = n & 63;
                    *(float2*)&C[(((size_t)(b * cNH + h) * cS + s) * cHD) + d] = v;
                }
            }
        }
}

// ===========================================================================
// scores_mma: 512 threads, 128x128, K=64 one-shot (stride 72 bf16 = 144 B).
// Raw masked scores + LSE partials. Warps 4x4, warp tile 32x32, ldmatrix.
// ===========================================================================
__global__ __launch_bounds__(512)
void scores_mma(const int* __restrict__ mask, float* __restrict__ attn)
{
    extern __shared__ char smraw[];
    __nv_bfloat16* Qh = (__nv_bfloat16*)smraw;    // 128*72 each
    __nv_bfloat16* Ql = Qh + 9216;
    __nv_bfloat16* Kh = Qh + 2 * 9216;
    __nv_bfloat16* Kl = Qh + 3 * 9216;
    __shared__ float s_m[128][4];
    __shared__ float s_s[128][4];
    const int t = threadIdx.x, lane = t & 31, wid = t >> 5;
    const int wm = wid >> 2, wn = wid & 3;
    const int gid = lane >> 2, tig = lane & 3;
    const int bh = blockIdx.z, b = bh >> 4;
    const int q0 = blockIdx.y * 128, n0 = blockIdx.x * 128;
    const float* Qm = g_Q + (size_t)bh * cS * cHD;
    const float* Km = g_K + (size_t)bh * cS * cHD;

    const uint32_t uQh = smem_u32(Qh);
    const uint32_t uQl = uQh + 9216 * 2;
    const uint32_t uKh = uQh + 2 * 9216 * 2;
    const uint32_t uKl = uQh + 3 * 9216 * 2;
    const uint32_t laneA = ldsmA_off(lane, 144) + (uint32_t)(wm * 32 * 144);
    const uint32_t laneB = ldsmB_off(lane, 144) + (uint32_t)(wn * 32 * 144);

#pragma unroll
    for (int i = 0; i < 4; i++) {
        int idx = t + i * 512, r = idx >> 4, kq = idx & 15;
        uint2 hp, lp;
        float4 v = *(const float4*)&Qm[(size_t)(q0 + r) * 64 + kq * 4];
        split4_pk(v, hp, lp);
        *(uint2*)&Qh[r * 72 + kq * 4] = hp;
        *(uint2*)&Ql[r * 72 + kq * 4] = lp;
        v = *(const float4*)&Km[(size_t)(n0 + r) * 64 + kq * 4];
        split4_pk(v, hp, lp);
        *(uint2*)&Kh[r * 72 + kq * 4] = hp;
        *(uint2*)&Kl[r * 72 + kq * 4] = lp;
    }
    __syncthreads();

    float c[2][4][4] = {};
#pragma unroll
    for (int kk = 0; kk < 4; kk++) {
        uint32_t ah[2][4], al[2][4], bh2[4][2], bl2[4][2];
        const uint32_t ko = (uint32_t)kk * 32;
#pragma unroll
        for (int mi = 0; mi < 2; mi++) {
            uint32_t ao = laneA + (uint32_t)(mi * 16 * 144) + ko;
            ldsm_x4(ah[mi][0], ah[mi][1], ah[mi][2], ah[mi][3], uQh + ao);
            ldsm_x4(al[mi][0], al[mi][1], al[mi][2], al[mi][3], uQl + ao);
        }
#pragma unroll
        for (int p = 0; p < 2; p++) {
            uint32_t bo = laneB + (uint32_t)(p * 16 * 144) + ko;
            ldsm_x4(bh2[2*p][0], bh2[2*p][1], bh2[2*p+1][0], bh2[2*p+1][1], uKh + bo);
            ldsm_x4(bl2[2*p][0], bl2[2*p][1], bl2[2*p+1][0], bl2[2*p+1][1], uKl + bo);
        }
#pragma unroll
        for (int mi = 0; mi < 2; mi++)
#pragma unroll
            for (int ni = 0; ni < 4; ni++) {
                mma_bf16(c[mi][ni], al[mi], bh2[ni]);
                mma_bf16(c[mi][ni], ah[mi], bl2[ni]);
                mma_bf16(c[mi][ni], ah[mi], bh2[ni]);
            }
    }

    const float patv = g_pat[bh] * cSCALE;
    const size_t mbase = (size_t)b * cS * cS;
    const size_t abase = (size_t)bh * cS * cS;
#pragma unroll
    for (int mi = 0; mi < 2; mi++)
#pragma unroll
        for (int half = 0; half < 2; half++) {
            int lr = wm * 32 + mi * 16 + half * 8 + gid;
            int q = q0 + lr;
            float vals[8];
            float mx = -CUDART_INF_F;
#pragma unroll
            for (int ni = 0; ni < 4; ni++) {
                int col = n0 + wn * 32 + ni * 8 + tig * 2;
                float2 v;
                v.x = c[mi][ni][half * 2 + 0] * patv;
                v.y = c[mi][ni][half * 2 + 1] * patv;
                int2 mk = *(const int2*)&mask[mbase + (size_t)q * cS + col];
                if (mk.x == 0) v.x = -1e9f;
                if (mk.y == 0) v.y = -1e9f;
                *(float2*)&attn[abase + (size_t)q * cS + col] = v;
                vals[ni * 2] = v.x; vals[ni * 2 + 1] = v.y;
                mx = fmaxf(mx, fmaxf(v.x, v.y));
            }
            mx = fmaxf(mx, __shfl_xor_sync(0xffffffff, mx, 1));
            mx = fmaxf(mx, __shfl_xor_sync(0xffffffff, mx, 2));
            float s = 0.f;
#pragma unroll
            for (int j = 0; j < 8; j++) s += __expf(vals[j] - mx);
            s += __shfl_xor_sync(0xffffffff, s, 1);
            s += __shfl_xor_sync(0xffffffff, s, 2);
            if (tig == 0) { s_m[lr][wn] = mx; s_s[lr][wn] = s; }
        }
    __syncthreads();
    if (t < 128) {
        float M = fmaxf(fmaxf(s_m[t][0], s_m[t][1]), fmaxf(s_m[t][2], s_m[t][3]));
        float S = s_s[t][0] * __expf(s_m[t][0] - M) + s_s[t][1] * __expf(s_m[t][1] - M)
                + s_s[t][2] * __expf(s_m[t][2] - M) + s_s[t][3] * __expf(s_m[t][3] - M);
        g_pstats[((size_t)bh * cS + q0 + t) * 16 + blockIdx.x] = make_float2(M, S);
    }
}

__global__ __launch_bounds__(256)
void merge_stats()
{
    const int idx = blockIdx.x * 256 + threadIdx.x;
    const float2* ps = &g_pstats[(size_t)idx * 16];
    float M = -CUDART_INF_F;
#pragma unroll
    for (int j = 0; j < 16; j++) M = fmaxf(M, ps[j].x);
    float S = 0.f;
#pragma unroll
    for (int j = 0; j < 16; j++) S += ps[j].y * __expf(ps[j].x - M);
    g_rowstats[idx] = make_float2(M, 1.0f / S);
}

// ===========================================================================
// context_mma (fused softmax): 512 threads, block 128x64, K=2048, warps
// 4(m) x 4(n), warp tile 32x16, ldmatrix. p written in place.
// ===========================================================================
__global__ __launch_bounds__(512)
void context_mma(float* attn)
{
    extern __shared__ char smraw[];
    __nv_bfloat16* Ah = (__nv_bfloat16*)smraw;   // [2][128*40]
    __nv_bfloat16* Al = Ah + 2 * 5120;
    __nv_bfloat16* Bh = Ah + 4 * 5120;           // [2][64*40]
    __nv_bfloat16* Bl = Ah + 4 * 5120 + 2 * 2560;
    __shared__ float sm_m[128], sm_i[128];
    const int t = threadIdx.x, lane = t & 31, wid = t >> 5;
    const int wm = wid >> 2, wn = wid & 3;
    const int gid = lane >> 2, tig = lane & 3;
    const int bh = blockIdx.y, q0 = blockIdx.x * 128;
    const int b = bh >> 4, h = bh & 15;
    float* Am = attn + (size_t)bh * cS * cS;
    const float* Vm = g_V + (size_t)bh * cS * cHD;

    const uint32_t uAh = smem_u32(Ah);
    const uint32_t uAl = uAh + 2 * 5120 * 2;
    const uint32_t uBh = uAh + 4 * 5120 * 2;
    const uint32_t uBl = uAh + (4 * 5120 + 2 * 2560) * 2;
    const uint32_t laneA = ldsmA_off(lane, 80) + (uint32_t)(wm * 32 * 80);
    const uint32_t laneB = ldsmB_off(lane, 80) + (uint32_t)(wn * 16 * 80);

    if (t < 128) {
        float2 rs = g_rowstats[(size_t)bh * cS + q0 + t];
        sm_m[t] = rs.x; sm_i[t] = rs.y;
    }

    float c[2][2][4] = {};
    float4 rA[2], rB;

#pragma unroll
    for (int i = 0; i < 2; i++) {
        int idx = t + i * 512, r = idx >> 3, kq = idx & 7;
        rA[i] = *(const float4*)&Am[(size_t)(q0 + r) * cS + kq * 4];
    }
    {
        int sl = t >> 4, dq = t & 15;
        rB = *(const float4*)&Vm[(size_t)sl * 64 + dq * 4];
    }
    __syncthreads();  // sm_m/sm_i visible
#pragma unroll
    for (int i = 0; i < 2; i++) {
        int idx = t + i * 512, r = idx >> 3, kq = idx & 7;
        float mm = sm_m[r], ii = sm_i[r];
        float4 p;
        p.x = __expf(rA[i].x - mm) * ii;
        p.y = __expf(rA[i].y - mm) * ii;
        p.z = __expf(rA[i].z - mm) * ii;
        p.w = __expf(rA[i].w - mm) * ii;
        *(float4*)&Am[(size_t)(q0 + r) * cS + kq * 4] = p;
        uint2 hp, lp;
        split4_pk(p, hp, lp);
        *(uint2*)&Ah[r * 40 + kq * 4] = hp;
        *(uint2*)&Al[r * 40 + kq * 4] = lp;
    }
    {
        int sl = t >> 4, dq = t & 15;
        const float vv[4] = {rB.x, rB.y, rB.z, rB.w};
#pragma unroll
        for (int j = 0; j < 4; j++) {
            __nv_bfloat16 hh, ll;
            split1(vv[j], hh, ll);
            Bh[(dq * 4 + j) * 40 + sl] = hh;
            Bl[(dq * 4 + j) * 40 + sl] = ll;
        }
    }
    __syncthreads();

    const int T = 64;
    for (int ch = 0; ch < T; ch++) {
        const int cur = ch & 1;
        if (ch + 1 < T) {
#pragma unroll
            for (int i = 0; i < 2; i++) {
                int idx = t + i * 512, r = idx >> 3, kq = idx & 7;
                rA[i] = *(const float4*)&Am[(size_t)(q0 + r) * cS + (ch + 1) * 32 + kq * 4];
            }
            {
                int sl = t >> 4, dq = t & 15;
                rB = *(const float4*)&Vm[(size_t)((ch + 1) * 32 + sl) * 64 + dq * 4];
            }
        }
        const uint32_t bufA = (uint32_t)cur * 10240;
        const uint32_t bufB = (uint32_t)cur * 5120;
#pragma unroll
        for (int kk = 0; kk < 2; kk++) {
            uint32_t ah[2][4], al[2][4], bh2[2][2], bl2[2][2];
            const uint32_t ko = (uint32_t)kk * 32;
#pragma unroll
            for (int mi = 0; mi < 2; mi++) {
                uint32_t ao = bufA + laneA + (uint32_t)(mi * 16 * 80) + ko;
                ldsm_x4(ah[mi][0], ah[mi][1], ah[mi][2], ah[mi][3], uAh + ao);
                ldsm_x4(al[mi][0], al[mi][1], al[mi][2], al[mi][3], uAl + ao);
            }
            {
                uint32_t bo = bufB + laneB + ko;
                ldsm_x4(bh2[0][0], bh2[0][1], bh2[1][0], bh2[1][1], uBh + bo);
                ldsm_x4(bl2[0][0], bl2[0][1], bl2[1][0], bl2[1][1], uBl + bo);
            }
#pragma unroll
            for (int mi = 0; mi < 2; mi++)
#pragma unroll
                for (int ni = 0; ni < 2; ni++) {
                    mma_bf16(c[mi][ni], al[mi], bh2[ni]);
                    mma_bf16(c[mi][ni], ah[mi], bl2[ni]);
                    mma_bf16(c[mi][ni], ah[mi], bh2[ni]);
                }
        }
        __syncthreads();
        if (ch + 1 < T) {
            __nv_bfloat16* Ahw = Ah + (cur ^ 1) * 5120;
            __nv_bfloat16* Alw = Al + (cur ^ 1) * 5120;
            __nv_bfloat16* Bhw = Bh + (cur ^ 1) * 2560;
            __nv_bfloat16* Blw = Bl + (cur ^ 1) * 2560;
#pragma unroll
            for (int i = 0; i < 2; i++) {
                int idx = t + i * 512, r = idx >> 3, kq = idx & 7;
                float mm = sm_m[r], ii = sm_i[r];
                float4 p;
                p.x = __expf(rA[i].x - mm) * ii;
                p.y = __expf(rA[i].y - mm) * ii;
                p.z = __expf(rA[i].z - mm) * ii;
                p.w = __expf(rA[i].w - mm) * ii;
                *(float4*)&Am[(size_t)(q0 + r) * cS + (ch + 1) * 32 + kq * 4] = p;
                uint2 hp, lp;
                split4_pk(p, hp, lp);
                *(uint2*)&Ahw[r * 40 + kq * 4] = hp;
                *(uint2*)&Alw[r * 40 + kq * 4] = lp;
            }
            {
                int sl = t >> 4, dq = t & 15;
                const float vv[4] = {rB.x, rB.y, rB.z, rB.w};
#pragma unroll
                for (int j = 0; j < 4; j++) {
                    __nv_bfloat16 hh, ll;
                    split1(vv[j], hh, ll);
                    Bhw[(dq * 4 + j) * 40 + sl] = hh;
                    Blw[(dq * 4 + j) * 40 + sl] = ll;
                }
            }
            __syncthreads();
        }
    }

#pragma unroll
    for (int mi = 0; mi < 2; mi++)
#pragma unroll
        for (int half = 0; half < 2; half++) {
            int s = q0 + wm * 32 + mi * 16 + gid + half * 8;
#pragma unroll
            for (int ni = 0; ni < 2; ni++) {
                int n = wn * 16 + ni * 8 + tig * 2;
                float2 v;
                v.x = c[mi][ni][half * 2 + 0];
                v.y = c[mi][ni][half * 2 + 1];
                *(float2*)&g_ctx[((size_t)(b * cS + s)) * cHS + h * cHD + n] = v;
            }
        }
}

// ===========================================================================
// Weight transpose + pattern selector (unchanged from R11)
// ===========================================================================
__global__ void transpose_w(const float* __restrict__ W0, const float* __restrict__ W1,
                            const float* __restrict__ W2, const float* __restrict__ W3)
{
    __shared__ float tile[32][33];
    const float* W = blockIdx.z == 0 ? W0 : blockIdx.z == 1 ? W1 : blockIdx.z == 2 ? W2 : W3;
    float* O = g_WT + (size_t)blockIdx.z * cHS * cHS;
    int x = blockIdx.x * 32 + threadIdx.x;
    int y0 = blockIdx.y * 32;
#pragma unroll
    for (int i = 0; i < 4; i++)
        tile[threadIdx.y + i * 8][threadIdx.x] = W[(size_t)(y0 + threadIdx.y + i * 8) * cHS + x];
    __syncthreads();
    int nx = blockIdx.y * 32 + threadIdx.x;
    int ny0 = blockIdx.x * 32;
#pragma unroll
    for (int i = 0; i < 4; i++)
        O[(size_t)(ny0 + threadIdx.y + i * 8) * cHS + nx] = tile[threadIdx.x][threadIdx.y + i * 8];
}

__global__ void qmean_partial(const float* __restrict__ query)
{
    const int b = blockIdx.y, tile = blockIdx.x;
    const int t = threadIdx.x;
    const int r0 = tile * 128;
    float s1 = 0.f, s2 = 0.f;
    for (int r = 0; r < 128; r++) {
        const float* base = query + ((size_t)b * cS + r0 + r) * cHS;
        s1 += base[t];
        s2 += base[t + 512];
    }
    g_qpart[(b * 16 + tile) * cHS + t] = s1;
    g_qpart[(b * 16 + tile) * cHS + t + 512] = s2;
}

__global__ __launch_bounds__(512)
void pattern_kernel(const float* __restrict__ Wp1, const float* __restrict__ bp1,
                    const float* __restrict__ Wp2, const float* __restrict__ bp2,
                    const float* __restrict__ patterns)
{
    const int b = blockIdx.x;
    const int t = threadIdx.x;
    __shared__ float qm[cHS];
    __shared__ float hb[cHS / 2];
    __shared__ float pw[cNP];
    for (int c = t; c < cHS; c += 512) {
        float s = 0.f;
        for (int p = 0; p < 16; p++) s += g_qpart[(b * 16 + p) * cHS + c];
        qm[c] = s * (1.0f / cS);
    }
    __syncthreads();
    {
        float a = bp1[t];
        for (int c = 0; c < cHS; c++) a += qm[c] * Wp1[c * (cHS / 2) + t];
        hb[t] = fmaxf(a, 0.f);
    }
    __syncthreads();
    __shared__ float lg[cNP];
    if (t < cNP) {
        float a = bp2[t];
        for (int j = 0; j < cHS / 2; j++) a += hb[j] * Wp2[j * cNP + t];
        lg[t] = a;
    }
    __syncthreads();
    if (t == 0) {
        float mx = lg[0];
        for (int p = 1; p < cNP; p++) mx = fmaxf(mx, lg[p]);
        float s = 0.f;
        for (int p = 0; p < cNP; p++) { pw[p] = __expf(lg[p] - mx); s += pw[p]; }
        float inv = 1.0f / s;
        for (int p = 0; p < cNP; p++) pw[p] *= inv;
    }
    __syncthreads();
    if (t < cNH) {
        float a = 0.f;
        for (int p = 0; p < cNP; p++) a += pw[p] * patterns[p * cNH + t];
        g_pat[b * cNH + t] = a;
    }
}

// ===========================================================================
// kernel_launch
// ===========================================================================
extern "C" void kernel_launch(void* const* d_in, const int* in_sizes, int n_in,
                              void* d_out, int out_size)
{
    const float* query = (const float*)d_in[0];
    const float* key   = (const float*)d_in[1];
    const float* value = (const float*)d_in[2];
    const int*   mask  = (const int*)d_in[3];
    const float* Wq  = (const float*)d_in[4];  const float* bq  = (const float*)d_in[5];
    const float* Wk  = (const float*)d_in[6];  const float* bk  = (const float*)d_in[7];
    const float* Wv  = (const float*)d_in[8];  const float* bv  = (const float*)d_in[9];
    const float* Wo  = (const float*)d_in[10]; const float* bo  = (const float*)d_in[11];
    const float* Wp1 = (const float*)d_in[12]; const float* bp1 = (const float*)d_in[13];
    const float* Wp2 = (const float*)d_in[14]; const float* bp2 = (const float*)d_in[15];
    const float* patterns = (const float*)d_in[16];
    float* out = (float*)d_out;

    void *pQ, *pK, *pV, *pCtx, *pWT;
    cudaGetSymbolAddress(&pQ, g_Q);
    cudaGetSymbolAddress(&pK, g_K);
    cudaGetSymbolAddress(&pV, g_V);
    cudaGetSymbolAddress(&pCtx, g_ctx);
    cudaGetSymbolAddress(&pWT, g_WT);
    const float* WT = (const float*)pWT;

    float* attn;
    if ((long)out_size >= OUT_ELEMS + ATTN_ELEMS) {
        attn = out + OUT_ELEMS;
    } else {
        void* pa;
        cudaGetSymbolAddress(&pa, g_attn_fallback);
        attn = (float*)pa;
    }

    const int SM_GEMM   = 8 * 5120 * 2;               // 81920
    const int SM_SCORES = 4 * 9216 * 2;               // 73728
    const int SM_CTX    = (4 * 5120 + 4 * 2560) * 2;  // 61440
    cudaFuncSetAttribute(gemm_bf<1>,  cudaFuncAttributeMaxDynamicSharedMemorySize, SM_GEMM);
    cudaFuncSetAttribute(gemm_bf<0>,  cudaFuncAttributeMaxDynamicSharedMemorySize, SM_GEMM);
    cudaFuncSetAttribute(scores_mma,  cudaFuncAttributeMaxDynamicSharedMemorySize, SM_SCORES);
    cudaFuncSetAttribute(context_mma, cudaFuncAttributeMaxDynamicSharedMemorySize, SM_CTX);

    // 1. pattern selector
    qmean_partial<<<dim3(16, cB), 512>>>(query);
    pattern_kernel<<<cB, 512>>>(Wp1, bp1, Wp2, bp2, patterns);

    // 2. transpose weights
    transpose_w<<<dim3(32, 32, 4), dim3(32, 8)>>>(Wq, Wk, Wv, Wo);

    // 3. merged QKV projection -> [B,NH,S,HD]
    dim3 gProj(cHS / 128, (cB * cS) / 128, 3);
    gemm_bf<1><<<gProj, 512, SM_GEMM>>>(query, key, value, WT, bq, bk, bv,
                                        (float*)pQ, (float*)pK, (float*)pV);

    // 4. raw scores + LSE partials
    dim3 gScores(cS / 128, cS / 128, cB * cNH);
    scores_mma<<<gScores, 512, SM_SCORES>>>(mask, attn);

    // 5. merge row stats
    merge_stats<<<(cB * cNH * cS) / 256, 256>>>();

    // 6. fused softmax + context
    dim3 gCtx(cS / 128, cB * cNH);
    context_mma<<<gCtx, 512, SM_CTX>>>(attn);

    // 7. output projection
    dim3 gOut(cHS / 128, (cB * cS) / 128, 1);
    gemm_bf<0><<<gOut, 512, SM_GEMM>>>((const float*)pCtx, nullptr, nullptr,
                                       WT + 3L * cHS * cHS, bo, nullptr, nullptr,
                                       out, nullptr, nullptr);
}

// round 15
// speedup vs baseline: 1.1245x; 1.1245x over previous
#include <cuda_runtime.h>
#include <cuda_bf16.h>
#include <cstdint>
#include <math_constants.h>

// ---------------------------------------------------------------------------
// AdaptiveAttention: B=2, S=2048, HS=1024, NH=16, HD=64, NP=8
// Round 15: R11 (best) + 2-term scores MMA (drop Q_lo·K_hi; pattern-scale
//           absorbs the error). Everything else byte-identical to R11.
// ---------------------------------------------------------------------------

constexpr int cB = 2, cS = 2048, cHS = 1024, cNH = 16, cNP = 8, cHD = 64;
constexpr float cSCALE = 0.125f;
constexpr long OUT_ELEMS  = (long)cB * cS * cHS;
constexpr long ATTN_ELEMS = (long)cB * cNH * cS * cS;

__device__ float g_Q[(long)cB * cNH * cS * cHD];
__device__ float g_K[(long)cB * cNH * cS * cHD];
__device__ float g_V[(long)cB * cNH * cS * cHD];     // [b,h,s,d]
__device__ float g_ctx[(long)cB * cS * cHS];
__device__ float g_pat[cB * cNH];
__device__ float g_WT[4L * cHS * cHS];
__device__ float g_qpart[32 * cHS];
__device__ float2 g_pstats[(long)cB * cNH * cS * 16];
__device__ float2 g_rowstats[(long)cB * cNH * cS];
__device__ float g_attn_fallback[ATTN_ELEMS];

// ---------------------------------------------------------------------------
__device__ __forceinline__ uint32_t smem_u32(const void* p) {
    uint32_t a;
    asm("{ .reg .u64 t; cvta.to.shared.u64 t, %1; cvt.u32.u64 %0, t; }" : "=r"(a) : "l"(p));
    return a;
}
__device__ __forceinline__ void mma_bf16(float c[4], const uint32_t a[4], const uint32_t b[2]) {
    asm volatile(
        "mma.sync.aligned.m16n8k16.row.col.f32.bf16.bf16.f32 "
        "{%0,%1,%2,%3}, {%4,%5,%6,%7}, {%8,%9}, {%0,%1,%2,%3};"
        : "+f"(c[0]), "+f"(c[1]), "+f"(c[2]), "+f"(c[3])
        : "r"(a[0]), "r"(a[1]), "r"(a[2]), "r"(a[3]), "r"(b[0]), "r"(b[1]));
}
__device__ __forceinline__ void ldsm_x4(uint32_t& r0, uint32_t& r1, uint32_t& r2, uint32_t& r3,
                                        uint32_t addr) {
    asm volatile("ldmatrix.sync.aligned.m8n8.x4.shared.b16 {%0,%1,%2,%3}, [%4];"
                 : "=r"(r0), "=r"(r1), "=r"(r2), "=r"(r3) : "r"(addr));
}
__device__ __forceinline__ uint32_t pk2(__nv_bfloat16 a, __nv_bfloat16 b) {
    __nv_bfloat162 t;
    t.x = a; t.y = b;
    return *(uint32_t*)&t;
}
__device__ __forceinline__ void split4_pk(float4 v, uint2& hp, uint2& lp) {
    __nv_bfloat16 h0 = __float2bfloat16_rn(v.x);
    __nv_bfloat16 h1 = __float2bfloat16_rn(v.y);
    __nv_bfloat16 h2 = __float2bfloat16_rn(v.z);
    __nv_bfloat16 h3 = __float2bfloat16_rn(v.w);
    __nv_bfloat16 l0 = __float2bfloat16_rn(v.x - __bfloat162float(h0));
    __nv_bfloat16 l1 = __float2bfloat16_rn(v.y - __bfloat162float(h1));
    __nv_bfloat16 l2 = __float2bfloat16_rn(v.z - __bfloat162float(h2));
    __nv_bfloat16 l3 = __float2bfloat16_rn(v.w - __bfloat162float(h3));
    hp.x = pk2(h0, h1); hp.y = pk2(h2, h3);
    lp.x = pk2(l0, l1); lp.y = pk2(l2, l3);
}
__device__ __forceinline__ uint2 hi4_pk(float4 v) {
    uint2 hp;
    hp.x = pk2(__float2bfloat16_rn(v.x), __float2bfloat16_rn(v.y));
    hp.y = pk2(__float2bfloat16_rn(v.z), __float2bfloat16_rn(v.w));
    return hp;
}
__device__ __forceinline__ void split1(float x, __nv_bfloat16& h, __nv_bfloat16& l) {
    h = __float2bfloat16_rn(x);
    l = __float2bfloat16_rn(x - __bfloat162float(h));
}
__device__ __forceinline__ uint32_t ldsmA_off(int lane, int rowbytes) {
    int row = (lane & 7) + (((lane >> 3) & 1) << 3);
    int k8  = (lane >> 4) & 1;
    return (uint32_t)(row * rowbytes + k8 * 16);
}
__device__ __forceinline__ uint32_t ldsmB_off(int lane, int rowbytes) {
    int row = (lane & 7) + (((lane >> 4) & 1) << 3);
    int k8  = (lane >> 3) & 1;
    return (uint32_t)(row * rowbytes + k8 * 16);
}

// ===========================================================================
// gemm_bf: 256 threads, block 128x128, K-chunk 32, warps 4(m) x 2(n),
// warp tile 32x64. ldmatrix fragment loads. MODE 1: merged QKV. MODE 0: plain.
// ===========================================================================
template <int MODE>
__global__ __launch_bounds__(256)
void gemm_bf(const float* __restrict__ A0, const float* __restrict__ A1,
             const float* __restrict__ A2, const float* __restrict__ WT,
             const float* __restrict__ b0v, const float* __restrict__ b1v,
             const float* __restrict__ b2v,
             float* __restrict__ C0, float* __restrict__ C1, float* __restrict__ C2)
{
    extern __shared__ char smraw[];
    __nv_bfloat16* Ah = (__nv_bfloat16*)smraw;        // [2][128*40]
    const int z = (MODE == 1) ? blockIdx.z : 0;
    const float* A    = z == 0 ? A0 : (z == 1 ? A1 : A2);
    const float* Bt   = WT + (size_t)z * cHS * cHS;
    const float* bias = z == 0 ? b0v : (z == 1 ? b1v : b2v);
    float* C          = z == 0 ? C0 : (z == 1 ? C1 : C2);

    const int t = threadIdx.x, lane = t & 31, wid = t >> 5;
    const int wm = wid >> 1, wn = wid & 1;
    const int gid = lane >> 2, tig = lane & 3;
    const int m0 = blockIdx.y * 128, n0 = blockIdx.x * 128;

    const uint32_t uAh = smem_u32(Ah);
    const uint32_t uAl = uAh + 2 * 5120 * 2;
    const uint32_t uBh = uAh + 4 * 5120 * 2;
    const uint32_t uBl = uAh + 6 * 5120 * 2;
    const uint32_t laneA = ldsmA_off(lane, 80) + (uint32_t)(wm * 32 * 80);
    const uint32_t laneB = ldsmB_off(lane, 80) + (uint32_t)(wn * 64 * 80);

    float c[2][8][4] = {};
    float4 rA[4], rB[4];

#pragma unroll
    for (int i = 0; i < 4; i++) {
        int idx = t + i * 256, r = idx >> 3, kq = idx & 7;
        rA[i] = *(const float4*)&A[(size_t)(m0 + r) * 1024 + kq * 4];
        rB[i] = *(const float4*)&Bt[(size_t)(n0 + r) * 1024 + kq * 4];
    }
    {
        __nv_bfloat16* Al = Ah + 2 * 5120;
        __nv_bfloat16* Bh = Ah + 4 * 5120;
        __nv_bfloat16* Bl = Ah + 6 * 5120;
#pragma unroll
        for (int i = 0; i < 4; i++) {
            int idx = t + i * 256, r = idx >> 3, kq = idx & 7;
            uint2 hp, lp;
            split4_pk(rA[i], hp, lp);
            *(uint2*)&Ah[r * 40 + kq * 4] = hp;
            *(uint2*)&Al[r * 40 + kq * 4] = lp;
            split4_pk(rB[i], hp, lp);
            *(uint2*)&Bh[r * 40 + kq * 4] = hp;
            *(uint2*)&Bl[r * 40 + kq * 4] = lp;
        }
    }
    __syncthreads();

    const int T = 32;
    for (int ch = 0; ch < T; ch++) {
        const int cur = ch & 1;
        if (ch + 1 < T) {
#pragma unroll
            for (int i = 0; i < 4; i++) {
                int idx = t + i * 256, r = idx >> 3, kq = idx & 7;
                rA[i] = *(const float4*)&A[(size_t)(m0 + r) * 1024 + (ch + 1) * 32 + kq * 4];
                rB[i] = *(const float4*)&Bt[(size_t)(n0 + r) * 1024 + (ch + 1) * 32 + kq * 4];
            }
        }
        const uint32_t bufo = (uint32_t)cur * 10240;
#pragma unroll
        for (int kk = 0; kk < 2; kk++) {
            uint32_t ah[2][4], al[2][4], bh[8][2], bl[8][2];
            const uint32_t ko = (uint32_t)kk * 32;
#pragma unroll
            for (int mi = 0; mi < 2; mi++) {
                uint32_t ao = bufo + laneA + (uint32_t)(mi * 16 * 80) + ko;
                ldsm_x4(ah[mi][0], ah[mi][1], ah[mi][2], ah[mi][3], uAh + ao);
                ldsm_x4(al[mi][0], al[mi][1], al[mi][2], al[mi][3], uAl + ao);
            }
#pragma unroll
            for (int p = 0; p < 4; p++) {
                uint32_t bo = bufo + laneB + (uint32_t)(p * 16 * 80) + ko;
                ldsm_x4(bh[2*p][0], bh[2*p][1], bh[2*p+1][0], bh[2*p+1][1], uBh + bo);
                ldsm_x4(bl[2*p][0], bl[2*p][1], bl[2*p+1][0], bl[2*p+1][1], uBl + bo);
            }
#pragma unroll
            for (int mi = 0; mi < 2; mi++)
#pragma unroll
                for (int ni = 0; ni < 8; ni++) {
                    mma_bf16(c[mi][ni], al[mi], bh[ni]);
                    mma_bf16(c[mi][ni], ah[mi], bl[ni]);
                    mma_bf16(c[mi][ni], ah[mi], bh[ni]);
                }
        }
        if (ch + 1 < T) {
            __syncthreads();
            __nv_bfloat16* Ahw = Ah + (cur ^ 1) * 5120;
            __nv_bfloat16* Alw = Ah + 2 * 5120 + (cur ^ 1) * 5120;
            __nv_bfloat16* Bhw = Ah + 4 * 5120 + (cur ^ 1) * 5120;
            __nv_bfloat16* Blw = Ah + 6 * 5120 + (cur ^ 1) * 5120;
#pragma unroll
            for (int i = 0; i < 4; i++) {
                int idx = t + i * 256, r = idx >> 3, kq = idx & 7;
                uint2 hp, lp;
                split4_pk(rA[i], hp, lp);
                *(uint2*)&Ahw[r * 40 + kq * 4] = hp;
                *(uint2*)&Alw[r * 40 + kq * 4] = lp;
                split4_pk(rB[i], hp, lp);
                *(uint2*)&Bhw[r * 40 + kq * 4] = hp;
                *(uint2*)&Blw[r * 40 + kq * 4] = lp;
            }
            __syncthreads();
        }
    }

#pragma unroll
    for (int mi = 0; mi < 2; mi++)
#pragma unroll
        for (int half = 0; half < 2; half++) {
            int m = m0 + wm * 32 + mi * 16 + gid + half * 8;
            int b = m >> 11, s = m & 2047;
#pragma unroll
            for (int ni = 0; ni < 8; ni++) {
                int n = n0 + wn * 64 + ni * 8 + tig * 2;
                float2 v;
                v.x = c[mi][ni][half * 2 + 0] + bias[n];
                v.y = c[mi][ni][half * 2 + 1] + bias[n + 1];
                if (MODE == 0) {
                    *(float2*)&C[(size_t)m * 1024 + n] = v;
                } else {
                    int h = n >> 6, d = n & 63;
                    *(float2*)&C[(((size_t)(b * cNH + h) * cS + s) * cHD) + d] = v;
                }
            }
        }
}

// ===========================================================================
// scores_mma: 256 threads, 128x128, K=64 one-shot (stride 72 bf16 = 144 B).
// 2-TERM split: uses Q_hi only (ah·bh + ah·bl); Q_lo smem/split removed.
// Raw masked scores + LSE partials. Warps 4x2, warp tile 32x64.
// ===========================================================================
__global__ __launch_bounds__(256)
void scores_mma(const int* __restrict__ mask, float* __restrict__ attn)
{
    extern __shared__ char smraw[];
    __nv_bfloat16* Qh = (__nv_bfloat16*)smraw;    // 128*72 each
    __nv_bfloat16* Kh = Qh + 9216;
    __nv_bfloat16* Kl = Qh + 2 * 9216;
    __shared__ float s_m[128][2];
    __shared__ float s_s[128][2];
    const int t = threadIdx.x, lane = t & 31, wid = t >> 5;
    const int wm = wid >> 1, wn = wid & 1;
    const int gid = lane >> 2, tig = lane & 3;
    const int bh = blockIdx.z, b = bh >> 4;
    const int q0 = blockIdx.y * 128, n0 = blockIdx.x * 128;
    const float* Qm = g_Q + (size_t)bh * cS * cHD;
    const float* Km = g_K + (size_t)bh * cS * cHD;

    const uint32_t uQh = smem_u32(Qh);
    const uint32_t uKh = uQh + 9216 * 2;
    const uint32_t uKl = uQh + 2 * 9216 * 2;
    const uint32_t laneA = ldsmA_off(lane, 144) + (uint32_t)(wm * 32 * 144);
    const uint32_t laneB = ldsmB_off(lane, 144) + (uint32_t)(wn * 64 * 144);

#pragma unroll
    for (int i = 0; i < 8; i++) {
        int idx = t + i * 256, r = idx >> 4, kq = idx & 15;
        float4 v = *(const float4*)&Qm[(size_t)(q0 + r) * 64 + kq * 4];
        *(uint2*)&Qh[r * 72 + kq * 4] = hi4_pk(v);
        v = *(const float4*)&Km[(size_t)(n0 + r) * 64 + kq * 4];
        uint2 hp, lp;
        split4_pk(v, hp, lp);
        *(uint2*)&Kh[r * 72 + kq * 4] = hp;
        *(uint2*)&Kl[r * 72 + kq * 4] = lp;
    }
    __syncthreads();

    float c[2][8][4] = {};
#pragma unroll
    for (int kk = 0; kk < 4; kk++) {
        uint32_t ah[2][4], bh2[8][2], bl2[8][2];
        const uint32_t ko = (uint32_t)kk * 32;
#pragma unroll
        for (int mi = 0; mi < 2; mi++) {
            uint32_t ao = laneA + (uint32_t)(mi * 16 * 144) + ko;
            ldsm_x4(ah[mi][0], ah[mi][1], ah[mi][2], ah[mi][3], uQh + ao);
        }
#pragma unroll
        for (int p = 0; p < 4; p++) {
            uint32_t bo = laneB + (uint32_t)(p * 16 * 144) + ko;
            ldsm_x4(bh2[2*p][0], bh2[2*p][1], bh2[2*p+1][0], bh2[2*p+1][1], uKh + bo);
            ldsm_x4(bl2[2*p][0], bl2[2*p][1], bl2[2*p+1][0], bl2[2*p+1][1], uKl + bo);
        }
#pragma unroll
        for (int mi = 0; mi < 2; mi++)
#pragma unroll
            for (int ni = 0; ni < 8; ni++) {
                mma_bf16(c[mi][ni], ah[mi], bl2[ni]);
                mma_bf16(c[mi][ni], ah[mi], bh2[ni]);
            }
    }

    const float patv = g_pat[bh] * cSCALE;
    const size_t mbase = (size_t)b * cS * cS;
    const size_t abase = (size_t)bh * cS * cS;
#pragma unroll
    for (int mi = 0; mi < 2; mi++)
#pragma unroll
        for (int half = 0; half < 2; half++) {
            int lr = wm * 32 + mi * 16 + half * 8 + gid;
            int q = q0 + lr;
            float vals[16];
            float mx = -CUDART_INF_F;
#pragma unroll
            for (int ni = 0; ni < 8; ni++) {
                int col = n0 + wn * 64 + ni * 8 + tig * 2;
                float2 v;
                v.x = c[mi][ni][half * 2 + 0] * patv;
                v.y = c[mi][ni][half * 2 + 1] * patv;
                int2 mk = *(const int2*)&mask[mbase + (size_t)q * cS + col];
                if (mk.x == 0) v.x = -1e9f;
                if (mk.y == 0) v.y = -1e9f;
                *(float2*)&attn[abase + (size_t)q * cS + col] = v;
                vals[ni * 2] = v.x; vals[ni * 2 + 1] = v.y;
                mx = fmaxf(mx, fmaxf(v.x, v.y));
            }
            mx = fmaxf(mx, __shfl_xor_sync(0xffffffff, mx, 1));
            mx = fmaxf(mx, __shfl_xor_sync(0xffffffff, mx, 2));
            float s = 0.f;
#pragma unroll
            for (int j = 0; j < 16; j++) s += __expf(vals[j] - mx);
            s += __shfl_xor_sync(0xffffffff, s, 1);
            s += __shfl_xor_sync(0xffffffff, s, 2);
            if (tig == 0) { s_m[lr][wn] = mx; s_s[lr][wn] = s; }
        }
    __syncthreads();
    if (t < 128) {
        float m0v = s_m[t][0], m1v = s_m[t][1];
        float s0v = s_s[t][0], s1v = s_s[t][1];
        float M = fmaxf(m0v, m1v);
        float S = s0v * __expf(m0v - M) + s1v * __expf(m1v - M);
        g_pstats[((size_t)bh * cS + q0 + t) * 16 + blockIdx.x] = make_float2(M, S);
    }
}

__global__ __launch_bounds__(256)
void merge_stats()
{
    const int idx = blockIdx.x * 256 + threadIdx.x;
    const float2* ps = &g_pstats[(size_t)idx * 16];
    float M = -CUDART_INF_F;
#pragma unroll
    for (int j = 0; j < 16; j++) M = fmaxf(M, ps[j].x);
    float S = 0.f;
#pragma unroll
    for (int j = 0; j < 16; j++) S += ps[j].y * __expf(ps[j].x - M);
    g_rowstats[idx] = make_float2(M, 1.0f / S);
}

// ===========================================================================
// context_mma (fused softmax): 256 threads, block 128x64, K=2048, warps
// 4(m) x 2(n), warp tile 32x32. ldmatrix loads; p written in place.
// ===========================================================================
__global__ __launch_bounds__(256)
void context_mma(float* attn)
{
    extern __shared__ char smraw[];
    __nv_bfloat16* Ah = (__nv_bfloat16*)smraw;   // [2][128*40]
    __nv_bfloat16* Al = Ah + 2 * 5120;
    __nv_bfloat16* Bh = Ah + 4 * 5120;           // [2][64*40]
    __nv_bfloat16* Bl = Ah + 4 * 5120 + 2 * 2560;
    __shared__ float sm_m[128], sm_i[128];
    const int t = threadIdx.x, lane = t & 31, wid = t >> 5;
    const int wm = wid >> 1, wn = wid & 1;
    const int gid = lane >> 2, tig = lane & 3;
    const int bh = blockIdx.y, q0 = blockIdx.x * 128;
    const int b = bh >> 4, h = bh & 15;
    float* Am = attn + (size_t)bh * cS * cS;
    const float* Vm = g_V + (size_t)bh * cS * cHD;

    const uint32_t uAh = smem_u32(Ah);
    const uint32_t uAl = uAh + 2 * 5120 * 2;
    const uint32_t uBh = uAh + 4 * 5120 * 2;
    const uint32_t uBl = uAh + (4 * 5120 + 2 * 2560) * 2;
    const uint32_t laneA = ldsmA_off(lane, 80) + (uint32_t)(wm * 32 * 80);
    const uint32_t laneB = ldsmB_off(lane, 80) + (uint32_t)(wn * 32 * 80);

    if (t < 128) {
        float2 rs = g_rowstats[(size_t)bh * cS + q0 + t];
        sm_m[t] = rs.x; sm_i[t] = rs.y;
    }

    float c[2][4][4] = {};
    float4 rA[4], rB[2];

#pragma unroll
    for (int i = 0; i < 4; i++) {
        int idx = t + i * 256, r = idx >> 3, kq = idx & 7;
        rA[i] = *(const float4*)&Am[(size_t)(q0 + r) * cS + kq * 4];
    }
#pragma unroll
    for (int i = 0; i < 2; i++) {
        int idx = t + i * 256, sl = idx >> 4, dq = idx & 15;
        rB[i] = *(const float4*)&Vm[(size_t)sl * 64 + dq * 4];
    }
    __syncthreads();  // sm_m/sm_i visible
#pragma unroll
    for (int i = 0; i < 4; i++) {
        int idx = t + i * 256, r = idx >> 3, kq = idx & 7;
        float mm = sm_m[r], ii = sm_i[r];
        float4 p;
        p.x = __expf(rA[i].x - mm) * ii;
        p.y = __expf(rA[i].y - mm) * ii;
        p.z = __expf(rA[i].z - mm) * ii;
        p.w = __expf(rA[i].w - mm) * ii;
        *(float4*)&Am[(size_t)(q0 + r) * cS + kq * 4] = p;
        uint2 hp, lp;
        split4_pk(p, hp, lp);
        *(uint2*)&Ah[r * 40 + kq * 4] = hp;
        *(uint2*)&Al[r * 40 + kq * 4] = lp;
    }
#pragma unroll
    for (int i = 0; i < 2; i++) {
        int idx = t + i * 256, sl = idx >> 4, dq = idx & 15;
        const float vv[4] = {rB[i].x, rB[i].y, rB[i].z, rB[i].w};
#pragma unroll
        for (int j = 0; j < 4; j++) {
            __nv_bfloat16 hh, ll;
            split1(vv[j], hh, ll);
            Bh[(dq * 4 + j) * 40 + sl] = hh;
            Bl[(dq * 4 + j) * 40 + sl] = ll;
        }
    }
    __syncthreads();

    const int T = 64;
    for (int ch = 0; ch < T; ch++) {
        const int cur = ch & 1;
        if (ch + 1 < T) {
#pragma unroll
            for (int i = 0; i < 4; i++) {
                int idx = t + i * 256, r = idx >> 3, kq = idx & 7;
                rA[i] = *(const float4*)&Am[(size_t)(q0 + r) * cS + (ch + 1) * 32 + kq * 4];
            }
#pragma unroll
            for (int i = 0; i < 2; i++) {
                int idx = t + i * 256, sl = idx >> 4, dq = idx & 15;
                rB[i] = *(const float4*)&Vm[(size_t)((ch + 1) * 32 + sl) * 64 + dq * 4];
            }
        }
        const uint32_t bufA = (uint32_t)cur * 10240;
        const uint32_t bufB = (uint32_t)cur * 5120;
#pragma unroll
        for (int kk = 0; kk < 2; kk++) {
            uint32_t ah[2][4], al[2][4], bh2[4][2], bl2[4][2];
            const uint32_t ko = (uint32_t)kk * 32;
#pragma unroll
            for (int mi = 0; mi < 2; mi++) {
                uint32_t ao = bufA + laneA + (uint32_t)(mi * 16 * 80) + ko;
                ldsm_x4(ah[mi][0], ah[mi][1], ah[mi][2], ah[mi][3], uAh + ao);
                ldsm_x4(al[mi][0], al[mi][1], al[mi][2], al[mi][3], uAl + ao);
            }
#pragma unroll
            for (int p = 0; p < 2; p++) {
                uint32_t bo = bufB + laneB + (uint32_t)(p * 16 * 80) + ko;
                ldsm_x4(bh2[2*p][0], bh2[2*p][1], bh2[2*p+1][0], bh2[2*p+1][1], uBh + bo);
                ldsm_x4(bl2[2*p][0], bl2[2*p][1], bl2[2*p+1][0], bl2[2*p+1][1], uBl + bo);
            }
#pragma unroll
            for (int mi = 0; mi < 2; mi++)
#pragma unroll
                for (int ni = 0; ni < 4; ni++) {
                    mma_bf16(c[mi][ni], al[mi], bh2[ni]);
                    mma_bf16(c[mi][ni], ah[mi], bl2[ni]);
                    mma_bf16(c[mi][ni], ah[mi], bh2[ni]);
                }
        }
        __syncthreads();
        if (ch + 1 < T) {
            __nv_bfloat16* Ahw = Ah + (cur ^ 1) * 5120;
            __nv_bfloat16* Alw = Al + (cur ^ 1) * 5120;
            __nv_bfloat16* Bhw = Bh + (cur ^ 1) * 2560;
            __nv_bfloat16* Blw = Bl + (cur ^ 1) * 2560;
#pragma unroll
            for (int i = 0; i < 4; i++) {
                int idx = t + i * 256, r = idx >> 3, kq = idx & 7;
                float mm = sm_m[r], ii = sm_i[r];
                float4 p;
                p.x = __expf(rA[i].x - mm) * ii;
                p.y = __expf(rA[i].y - mm) * ii;
                p.z = __expf(rA[i].z - mm) * ii;
                p.w = __expf(rA[i].w - mm) * ii;
                *(float4*)&Am[(size_t)(q0 + r) * cS + (ch + 1) * 32 + kq * 4] = p;
                uint2 hp, lp;
                split4_pk(p, hp, lp);
                *(uint2*)&Ahw[r * 40 + kq * 4] = hp;
                *(uint2*)&Alw[r * 40 + kq * 4] = lp;
            }
#pragma unroll
            for (int i = 0; i < 2; i++) {
                int idx = t + i * 256, sl = idx >> 4, dq = idx & 15;
                const float vv[4] = {rB[i].x, rB[i].y, rB[i].z, rB[i].w};
#pragma unroll
                for (int j = 0; j < 4; j++) {
                    __nv_bfloat16 hh, ll;
                    split1(vv[j], hh, ll);
                    Bhw[(dq * 4 + j) * 40 + sl] = hh;
                    Blw[(dq * 4 + j) * 40 + sl] = ll;
                }
            }
            __syncthreads();
        }
    }

#pragma unroll
    for (int mi = 0; mi < 2; mi++)
#pragma unroll
        for (int half = 0; half < 2; half++) {
            int s = q0 + wm * 32 + mi * 16 + gid + half * 8;
#pragma unroll
            for (int ni = 0; ni < 4; ni++) {
                int n = wn * 32 + ni * 8 + tig * 2;
                float2 v;
                v.x = c[mi][ni][half * 2 + 0];
                v.y = c[mi][ni][half * 2 + 1];
                *(float2*)&g_ctx[((size_t)(b * cS + s)) * cHS + h * cHD + n] = v;
            }
        }
}

// ===========================================================================
// Weight transpose + pattern selector (unchanged)
// ===========================================================================
__global__ void transpose_w(const float* __restrict__ W0, const float* __restrict__ W1,
                            const float* __restrict__ W2, const float* __restrict__ W3)
{
    __shared__ float tile[32][33];
    const float* W = blockIdx.z == 0 ? W0 : blockIdx.z == 1 ? W1 : blockIdx.z == 2 ? W2 : W3;
    float* O = g_WT + (size_t)blockIdx.z * cHS * cHS;
    int x = blockIdx.x * 32 + threadIdx.x;
    int y0 = blockIdx.y * 32;
#pragma unroll
    for (int i = 0; i < 4; i++)
        tile[threadIdx.y + i * 8][threadIdx.x] = W[(size_t)(y0 + threadIdx.y + i * 8) * cHS + x];
    __syncthreads();
    int nx = blockIdx.y * 32 + threadIdx.x;
    int ny0 = blockIdx.x * 32;
#pragma unroll
    for (int i = 0; i < 4; i++)
        O[(size_t)(ny0 + threadIdx.y + i * 8) * cHS + nx] = tile[threadIdx.x][threadIdx.y + i * 8];
}

__global__ void qmean_partial(const float* __restrict__ query)
{
    const int b = blockIdx.y, tile = blockIdx.x;
    const int t = threadIdx.x;
    const int r0 = tile * 128;
    float s1 = 0.f, s2 = 0.f;
    for (int r = 0; r < 128; r++) {
        const float* base = query + ((size_t)b * cS + r0 + r) * cHS;
        s1 += base[t];
        s2 += base[t + 512];
    }
    g_qpart[(b * 16 + tile) * cHS + t] = s1;
    g_qpart[(b * 16 + tile) * cHS + t + 512] = s2;
}

__global__ __launch_bounds__(512)
void pattern_kernel(const float* __restrict__ Wp1, const float* __restrict__ bp1,
                    const float* __restrict__ Wp2, const float* __restrict__ bp2,
                    const float* __restrict__ patterns)
{
    const int b = blockIdx.x;
    const int t = threadIdx.x;
    __shared__ float qm[cHS];
    __shared__ float hb[cHS / 2];
    __shared__ float pw[cNP];
    for (int c = t; c < cHS; c += 512) {
        float s = 0.f;
        for (int p = 0; p < 16; p++) s += g_qpart[(b * 16 + p) * cHS + c];
        qm[c] = s * (1.0f / cS);
    }
    __syncthreads();
    {
        float a = bp1[t];
        for (int c = 0; c < cHS; c++) a += qm[c] * Wp1[c * (cHS / 2) + t];
        hb[t] = fmaxf(a, 0.f);
    }
    __syncthreads();
    __shared__ float lg[cNP];
    if (t < cNP) {
        float a = bp2[t];
        for (int j = 0; j < cHS / 2; j++) a += hb[j] * Wp2[j * cNP + t];
        lg[t] = a;
    }
    __syncthreads();
    if (t == 0) {
        float mx = lg[0];
        for (int p = 1; p < cNP; p++) mx = fmaxf(mx, lg[p]);
        float s = 0.f;
        for (int p = 0; p < cNP; p++) { pw[p] = __expf(lg[p] - mx); s += pw[p]; }
        float inv = 1.0f / s;
        for (int p = 0; p < cNP; p++) pw[p] *= inv;
    }
    __syncthreads();
    if (t < cNH) {
        float a = 0.f;
        for (int p = 0; p < cNP; p++) a += pw[p] * patterns[p * cNH + t];
        g_pat[b * cNH + t] = a;
    }
}

// ===========================================================================
// kernel_launch
// ===========================================================================
extern "C" void kernel_launch(void* const* d_in, const int* in_sizes, int n_in,
                              void* d_out, int out_size)
{
    const float* query = (const float*)d_in[0];
    const float* key   = (const float*)d_in[1];
    const float* value = (const float*)d_in[2];
    const int*   mask  = (const int*)d_in[3];
    const float* Wq  = (const float*)d_in[4];  const float* bq  = (const float*)d_in[5];
    const float* Wk  = (const float*)d_in[6];  const float* bk  = (const float*)d_in[7];
    const float* Wv  = (const float*)d_in[8];  const float* bv  = (const float*)d_in[9];
    const float* Wo  = (const float*)d_in[10]; const float* bo  = (const float*)d_in[11];
    const float* Wp1 = (const float*)d_in[12]; const float* bp1 = (const float*)d_in[13];
    const float* Wp2 = (const float*)d_in[14]; const float* bp2 = (const float*)d_in[15];
    const float* patterns = (const float*)d_in[16];
    float* out = (float*)d_out;

    void *pQ, *pK, *pV, *pCtx, *pWT;
    cudaGetSymbolAddress(&pQ, g_Q);
    cudaGetSymbolAddress(&pK, g_K);
    cudaGetSymbolAddress(&pV, g_V);
    cudaGetSymbolAddress(&pCtx, g_ctx);
    cudaGetSymbolAddress(&pWT, g_WT);
    const float* WT = (const float*)pWT;

    float* attn;
    if ((long)out_size >= OUT_ELEMS + ATTN_ELEMS) {
        attn = out + OUT_ELEMS;
    } else {
        void* pa;
        cudaGetSymbolAddress(&pa, g_attn_fallback);
        attn = (float*)pa;
    }

    const int SM_GEMM   = 8 * 5120 * 2;               // 81920
    const int SM_SCORES = 3 * 9216 * 2;               // 55296
    const int SM_CTX    = (4 * 5120 + 4 * 2560) * 2;  // 61440
    cudaFuncSetAttribute(gemm_bf<1>,  cudaFuncAttributeMaxDynamicSharedMemorySize, SM_GEMM);
    cudaFuncSetAttribute(gemm_bf<0>,  cudaFuncAttributeMaxDynamicSharedMemorySize, SM_GEMM);
    cudaFuncSetAttribute(scores_mma,  cudaFuncAttributeMaxDynamicSharedMemorySize, SM_SCORES);
    cudaFuncSetAttribute(context_mma, cudaFuncAttributeMaxDynamicSharedMemorySize, SM_CTX);

    // 1. pattern selector
    qmean_partial<<<dim3(16, cB), 512>>>(query);
    pattern_kernel<<<cB, 512>>>(Wp1, bp1, Wp2, bp2, patterns);

    // 2. transpose weights
    transpose_w<<<dim3(32, 32, 4), dim3(32, 8)>>>(Wq, Wk, Wv, Wo);

    // 3. merged QKV projection -> [B,NH,S,HD]
    dim3 gProj(cHS / 128, (cB * cS) / 128, 3);
    gemm_bf<1><<<gProj, 256, SM_GEMM>>>(query, key, value, WT, bq, bk, bv,
                                        (float*)pQ, (float*)pK, (float*)pV);

    // 4. raw scores + LSE partials (2-term split)
    dim3 gScores(cS / 128, cS / 128, cB * cNH);
    scores_mma<<<gScores, 256, SM_SCORES>>>(mask, attn);

    // 5. merge row stats
    merge_stats<<<(cB * cNH * cS) / 256, 256>>>();

    // 6. fused softmax + context
    dim3 gCtx(cS / 128, cB * cNH);
    context_mma<<<gCtx, 256, SM_CTX>>>(attn);

    // 7. output projection
    dim3 gOut(cHS / 128, (cB * cS) / 128, 1);
    gemm_bf<0><<<gOut, 256, SM_GEMM>>>((const float*)pCtx, nullptr, nullptr,
                                       WT + 3L * cHS * cHS, bo, nullptr, nullptr,
                                       out, nullptr, nullptr);
}

// round 17
// speedup vs baseline: 1.1461x; 1.0192x over previous
#include <cuda_runtime.h>
#include <cuda_bf16.h>
#include <cstdint>
#include <math_constants.h>

// ---------------------------------------------------------------------------
// AdaptiveAttention: B=2, S=2048, HS=1024, NH=16, HD=64, NP=8
// Round 16: R15 + pure-bf16 scores (1-term) + 2-term Q/K projections
//           (pattern-scale absorbs score-path error). V/context/out stay full.
// ---------------------------------------------------------------------------

constexpr int cB = 2, cS = 2048, cHS = 1024, cNH = 16, cNP = 8, cHD = 64;
constexpr float cSCALE = 0.125f;
constexpr long OUT_ELEMS  = (long)cB * cS * cHS;
constexpr long ATTN_ELEMS = (long)cB * cNH * cS * cS;

__device__ float g_Q[(long)cB * cNH * cS * cHD];
__device__ float g_K[(long)cB * cNH * cS * cHD];
__device__ float g_V[(long)cB * cNH * cS * cHD];     // [b,h,s,d]
__device__ float g_ctx[(long)cB * cS * cHS];
__device__ float g_pat[cB * cNH];
__device__ float g_WT[4L * cHS * cHS];
__device__ float g_qpart[32 * cHS];
__device__ float2 g_pstats[(long)cB * cNH * cS * 16];
__device__ float2 g_rowstats[(long)cB * cNH * cS];
__device__ float g_attn_fallback[ATTN_ELEMS];

// ---------------------------------------------------------------------------
__device__ __forceinline__ uint32_t smem_u32(const void* p) {
    uint32_t a;
    asm("{ .reg .u64 t; cvta.to.shared.u64 t, %1; cvt.u32.u64 %0, t; }" : "=r"(a) : "l"(p));
    return a;
}
__device__ __forceinline__ void mma_bf16(float c[4], const uint32_t a[4], const uint32_t b[2]) {
    asm volatile(
        "mma.sync.aligned.m16n8k16.row.col.f32.bf16.bf16.f32 "
        "{%0,%1,%2,%3}, {%4,%5,%6,%7}, {%8,%9}, {%0,%1,%2,%3};"
        : "+f"(c[0]), "+f"(c[1]), "+f"(c[2]), "+f"(c[3])
        : "r"(a[0]), "r"(a[1]), "r"(a[2]), "r"(a[3]), "r"(b[0]), "r"(b[1]));
}
__device__ __forceinline__ void ldsm_x4(uint32_t& r0, uint32_t& r1, uint32_t& r2, uint32_t& r3,
                                        uint32_t addr) {
    asm volatile("ldmatrix.sync.aligned.m8n8.x4.shared.b16 {%0,%1,%2,%3}, [%4];"
                 : "=r"(r0), "=r"(r1), "=r"(r2), "=r"(r3) : "r"(addr));
}
__device__ __forceinline__ uint32_t pk2(__nv_bfloat16 a, __nv_bfloat16 b) {
    __nv_bfloat162 t;
    t.x = a; t.y = b;
    return *(uint32_t*)&t;
}
__device__ __forceinline__ void split4_pk(float4 v, uint2& hp, uint2& lp) {
    __nv_bfloat16 h0 = __float2bfloat16_rn(v.x);
    __nv_bfloat16 h1 = __float2bfloat16_rn(v.y);
    __nv_bfloat16 h2 = __float2bfloat16_rn(v.z);
    __nv_bfloat16 h3 = __float2bfloat16_rn(v.w);
    __nv_bfloat16 l0 = __float2bfloat16_rn(v.x - __bfloat162float(h0));
    __nv_bfloat16 l1 = __float2bfloat16_rn(v.y - __bfloat162float(h1));
    __nv_bfloat16 l2 = __float2bfloat16_rn(v.z - __bfloat162float(h2));
    __nv_bfloat16 l3 = __float2bfloat16_rn(v.w - __bfloat162float(h3));
    hp.x = pk2(h0, h1); hp.y = pk2(h2, h3);
    lp.x = pk2(l0, l1); lp.y = pk2(l2, l3);
}
__device__ __forceinline__ uint2 hi4_pk(float4 v) {
    uint2 hp;
    hp.x = pk2(__float2bfloat16_rn(v.x), __float2bfloat16_rn(v.y));
    hp.y = pk2(__float2bfloat16_rn(v.z), __float2bfloat16_rn(v.w));
    return hp;
}
__device__ __forceinline__ void split1(float x, __nv_bfloat16& h, __nv_bfloat16& l) {
    h = __float2bfloat16_rn(x);
    l = __float2bfloat16_rn(x - __bfloat162float(h));
}
__device__ __forceinline__ uint32_t ldsmA_off(int lane, int rowbytes) {
    int row = (lane & 7) + (((lane >> 3) & 1) << 3);
    int k8  = (lane >> 4) & 1;
    return (uint32_t)(row * rowbytes + k8 * 16);
}
__device__ __forceinline__ uint32_t ldsmB_off(int lane, int rowbytes) {
    int row = (lane & 7) + (((lane >> 4) & 1) << 3);
    int k8  = (lane >> 3) & 1;
    return (uint32_t)(row * rowbytes + k8 * 16);
}

// ===========================================================================
// gemm_bf: 256 threads, block 128x128, K-chunk 32, warps 4(m) x 2(n),
// warp tile 32x64, ldmatrix. MODE 1: merged QKV (z=0,1 use 2-term arithmetic;
// z=2 = V keeps full 3-term). MODE 0: plain row-major store (3-term).
// ===========================================================================
template <int MODE>
__global__ __launch_bounds__(256)
void gemm_bf(const float* __restrict__ A0, const float* __restrict__ A1,
             const float* __restrict__ A2, const float* __restrict__ WT,
             const float* __restrict__ b0v, const float* __restrict__ b1v,
             const float* __restrict__ b2v,
             float* __restrict__ C0, float* __restrict__ C1, float* __restrict__ C2)
{
    extern __shared__ char smraw[];
    __nv_bfloat16* Ah = (__nv_bfloat16*)smraw;        // [2][128*40]
    const int z = (MODE == 1) ? blockIdx.z : 0;
    const bool full = (MODE == 0) || (z == 2);
    const float* A    = z == 0 ? A0 : (z == 1 ? A1 : A2);
    const float* Bt   = WT + (size_t)z * cHS * cHS;
    const float* bias = z == 0 ? b0v : (z == 1 ? b1v : b2v);
    float* C          = z == 0 ? C0 : (z == 1 ? C1 : C2);

    const int t = threadIdx.x, lane = t & 31, wid = t >> 5;
    const int wm = wid >> 1, wn = wid & 1;
    const int gid = lane >> 2, tig = lane & 3;
    const int m0 = blockIdx.y * 128, n0 = blockIdx.x * 128;

    const uint32_t uAh = smem_u32(Ah);
    const uint32_t uAl = uAh + 2 * 5120 * 2;
    const uint32_t uBh = uAh + 4 * 5120 * 2;
    const uint32_t uBl = uAh + 6 * 5120 * 2;
    const uint32_t laneA = ldsmA_off(lane, 80) + (uint32_t)(wm * 32 * 80);
    const uint32_t laneB = ldsmB_off(lane, 80) + (uint32_t)(wn * 64 * 80);

    float c[2][8][4] = {};
    float4 rA[4], rB[4];

#pragma unroll
    for (int i = 0; i < 4; i++) {
        int idx = t + i * 256, r = idx >> 3, kq = idx & 7;
        rA[i] = *(const float4*)&A[(size_t)(m0 + r) * 1024 + kq * 4];
        rB[i] = *(const float4*)&Bt[(size_t)(n0 + r) * 1024 + kq * 4];
    }
    {
        __nv_bfloat16* Al = Ah + 2 * 5120;
        __nv_bfloat16* Bh = Ah + 4 * 5120;
        __nv_bfloat16* Bl = Ah + 6 * 5120;
#pragma unroll
        for (int i = 0; i < 4; i++) {
            int idx = t + i * 256, r = idx >> 3, kq = idx & 7;
            uint2 hp, lp;
            split4_pk(rA[i], hp, lp);
            *(uint2*)&Ah[r * 40 + kq * 4] = hp;
            *(uint2*)&Al[r * 40 + kq * 4] = lp;
            split4_pk(rB[i], hp, lp);
            *(uint2*)&Bh[r * 40 + kq * 4] = hp;
            *(uint2*)&Bl[r * 40 + kq * 4] = lp;
        }
    }
    __syncthreads();

    const int T = 32;
    for (int ch = 0; ch < T; ch++) {
        const int cur = ch & 1;
        if (ch + 1 < T) {
#pragma unroll
            for (int i = 0; i < 4; i++) {
                int idx = t + i * 256, r = idx >> 3, kq = idx & 7;
                rA[i] = *(const float4*)&A[(size_t)(m0 + r) * 1024 + (ch + 1) * 32 + kq * 4];
                rB[i] = *(const float4*)&Bt[(size_t)(n0 + r) * 1024 + (ch + 1) * 32 + kq * 4];
            }
        }
        const uint32_t bufo = (uint32_t)cur * 10240;
#pragma unroll
        for (int kk = 0; kk < 2; kk++) {
            uint32_t ah[2][4], al[2][4], bh[8][2], bl[8][2];
            const uint32_t ko = (uint32_t)kk * 32;
#pragma unroll
            for (int mi = 0; mi < 2; mi++) {
                uint32_t ao = bufo + laneA + (uint32_t)(mi * 16 * 80) + ko;
                ldsm_x4(ah[mi][0], ah[mi][1], ah[mi][2], ah[mi][3], uAh + ao);
                if (full)
                    ldsm_x4(al[mi][0], al[mi][1], al[mi][2], al[mi][3], uAl + ao);
            }
#pragma unroll
            for (int p = 0; p < 4; p++) {
                uint32_t bo = bufo + laneB + (uint32_t)(p * 16 * 80) + ko;
                ldsm_x4(bh[2*p][0], bh[2*p][1], bh[2*p+1][0], bh[2*p+1][1], uBh + bo);
                ldsm_x4(bl[2*p][0], bl[2*p][1], bl[2*p+1][0], bl[2*p+1][1], uBl + bo);
            }
            if (full) {
#pragma unroll
                for (int mi = 0; mi < 2; mi++)
#pragma unroll
                    for (int ni = 0; ni < 8; ni++) {
                        mma_bf16(c[mi][ni], al[mi], bh[ni]);
                        mma_bf16(c[mi][ni], ah[mi], bl[ni]);
                        mma_bf16(c[mi][ni], ah[mi], bh[ni]);
                    }
            } else {
#pragma unroll
                for (int mi = 0; mi < 2; mi++)
#pragma unroll
                    for (int ni = 0; ni < 8; ni++) {
                        mma_bf16(c[mi][ni], ah[mi], bl[ni]);
                        mma_bf16(c[mi][ni], ah[mi], bh[ni]);
                    }
            }
        }
        if (ch + 1 < T) {
            __syncthreads();
            __nv_bfloat16* Ahw = Ah + (cur ^ 1) * 5120;
            __nv_bfloat16* Alw = Ah + 2 * 5120 + (cur ^ 1) * 5120;
            __nv_bfloat16* Bhw = Ah + 4 * 5120 + (cur ^ 1) * 5120;
            __nv_bfloat16* Blw = Ah + 6 * 5120 + (cur ^ 1) * 5120;
#pragma unroll
            for (int i = 0; i < 4; i++) {
                int idx = t + i * 256, r = idx >> 3, kq = idx & 7;
                uint2 hp, lp;
                split4_pk(rA[i], hp, lp);
                *(uint2*)&Ahw[r * 40 + kq * 4] = hp;
                *(uint2*)&Alw[r * 40 + kq * 4] = lp;
                split4_pk(rB[i], hp, lp);
                *(uint2*)&Bhw[r * 40 + kq * 4] = hp;
                *(uint2*)&Blw[r * 40 + kq * 4] = lp;
            }
            __syncthreads();
        }
    }

#pragma unroll
    for (int mi = 0; mi < 2; mi++)
#pragma unroll
        for (int half = 0; half < 2; half++) {
            int m = m0 + wm * 32 + mi * 16 + gid + half * 8;
            int b = m >> 11, s = m & 2047;
#pragma unroll
            for (int ni = 0; ni < 8; ni++) {
                int n = n0 + wn * 64 + ni * 8 + tig * 2;
                float2 v;
                v.x = c[mi][ni][half * 2 + 0] + bias[n];
                v.y = c[mi][ni][half * 2 + 1] + bias[n + 1];
                if (MODE == 0) {
                    *(float2*)&C[(size_t)m * 1024 + n] = v;
                } else {
                    int h = n >> 6, d = n & 63;
                    *(float2*)&C[(((size_t)(b * cNH + h) * cS + s) * cHD) + d] = v;
                }
            }
        }
}

// ===========================================================================
// scores_mma: pure bf16 (1-term Q_hi·K_hi). 256 threads, 128x128, K=64.
// Raw masked scores + LSE partials. Warps 4x2, warp tile 32x64.
// smem: Qh + Kh only (36864 B).
// ===========================================================================
__global__ __launch_bounds__(256)
void scores_mma(const int* __restrict__ mask, float* __restrict__ attn)
{
    extern __shared__ char smraw[];
    __nv_bfloat16* Qh = (__nv_bfloat16*)smraw;    // 128*72 each
    __nv_bfloat16* Kh = Qh + 9216;
    __shared__ float s_m[128][2];
    __shared__ float s_s[128][2];
    const int t = threadIdx.x, lane = t & 31, wid = t >> 5;
    const int wm = wid >> 1, wn = wid & 1;
    const int gid = lane >> 2, tig = lane & 3;
    const int bh = blockIdx.z, b = bh >> 4;
    const int q0 = blockIdx.y * 128, n0 = blockIdx.x * 128;
    const float* Qm = g_Q + (size_t)bh * cS * cHD;
    const float* Km = g_K + (size_t)bh * cS * cHD;

    const uint32_t uQh = smem_u32(Qh);
    const uint32_t uKh = uQh + 9216 * 2;
    const uint32_t laneA = ldsmA_off(lane, 144) + (uint32_t)(wm * 32 * 144);
    const uint32_t laneB = ldsmB_off(lane, 144) + (uint32_t)(wn * 64 * 144);

#pragma unroll
    for (int i = 0; i < 8; i++) {
        int idx = t + i * 256, r = idx >> 4, kq = idx & 15;
        float4 v = *(const float4*)&Qm[(size_t)(q0 + r) * 64 + kq * 4];
        *(uint2*)&Qh[r * 72 + kq * 4] = hi4_pk(v);
        v = *(const float4*)&Km[(size_t)(n0 + r) * 64 + kq * 4];
        *(uint2*)&Kh[r * 72 + kq * 4] = hi4_pk(v);
    }
    __syncthreads();

    float c[2][8][4] = {};
#pragma unroll
    for (int kk = 0; kk < 4; kk++) {
        uint32_t ah[2][4], bh2[8][2];
        const uint32_t ko = (uint32_t)kk * 32;
#pragma unroll
        for (int mi = 0; mi < 2; mi++) {
            uint32_t ao = laneA + (uint32_t)(mi * 16 * 144) + ko;
            ldsm_x4(ah[mi][0], ah[mi][1], ah[mi][2], ah[mi][3], uQh + ao);
        }
#pragma unroll
        for (int p = 0; p < 4; p++) {
            uint32_t bo = laneB + (uint32_t)(p * 16 * 144) + ko;
            ldsm_x4(bh2[2*p][0], bh2[2*p][1], bh2[2*p+1][0], bh2[2*p+1][1], uKh + bo);
        }
#pragma unroll
        for (int mi = 0; mi < 2; mi++)
#pragma unroll
            for (int ni = 0; ni < 8; ni++)
                mma_bf16(c[mi][ni], ah[mi], bh2[ni]);
    }

    const float patv = g_pat[bh] * cSCALE;
    const size_t mbase = (size_t)b * cS * cS;
    const size_t abase = (size_t)bh * cS * cS;
#pragma unroll
    for (int mi = 0; mi < 2; mi++)
#pragma unroll
        for (int half = 0; half < 2; half++) {
            int lr = wm * 32 + mi * 16 + half * 8 + gid;
            int q = q0 + lr;
            float vals[16];
            float mx = -CUDART_INF_F;
#pragma unroll
            for (int ni = 0; ni < 8; ni++) {
                int col = n0 + wn * 64 + ni * 8 + tig * 2;
                float2 v;
                v.x = c[mi][ni][half * 2 + 0] * patv;
                v.y = c[mi][ni][half * 2 + 1] * patv;
                int2 mk = *(const int2*)&mask[mbase + (size_t)q * cS + col];
                if (mk.x == 0) v.x = -1e9f;
                if (mk.y == 0) v.y = -1e9f;
                *(float2*)&attn[abase + (size_t)q * cS + col] = v;
                vals[ni * 2] = v.x; vals[ni * 2 + 1] = v.y;
                mx = fmaxf(mx, fmaxf(v.x, v.y));
            }
            mx = fmaxf(mx, __shfl_xor_sync(0xffffffff, mx, 1));
            mx = fmaxf(mx, __shfl_xor_sync(0xffffffff, mx, 2));
            float s = 0.f;
#pragma unroll
            for (int j = 0; j < 16; j++) s += __expf(vals[j] - mx);
            s += __shfl_xor_sync(0xffffffff, s, 1);
            s += __shfl_xor_sync(0xffffffff, s, 2);
            if (tig == 0) { s_m[lr][wn] = mx; s_s[lr][wn] = s; }
        }
    __syncthreads();
    if (t < 128) {
        float m0v = s_m[t][0], m1v = s_m[t][1];
        float s0v = s_s[t][0], s1v = s_s[t][1];
        float M = fmaxf(m0v, m1v);
        float S = s0v * __expf(m0v - M) + s1v * __expf(m1v - M);
        g_pstats[((size_t)bh * cS + q0 + t) * 16 + blockIdx.x] = make_float2(M, S);
    }
}

__global__ __launch_bounds__(256)
void merge_stats()
{
    const int idx = blockIdx.x * 256 + threadIdx.x;
    const float2* ps = &g_pstats[(size_t)idx * 16];
    float M = -CUDART_INF_F;
#pragma unroll
    for (int j = 0; j < 16; j++) M = fmaxf(M, ps[j].x);
    float S = 0.f;
#pragma unroll
    for (int j = 0; j < 16; j++) S += ps[j].y * __expf(ps[j].x - M);
    g_rowstats[idx] = make_float2(M, 1.0f / S);
}

// ===========================================================================
// context_mma (fused softmax): 256 threads, block 128x64, K=2048, warps
// 4(m) x 2(n), warp tile 32x32, ldmatrix, full 3-term. p written in place.
// ===========================================================================
__global__ __launch_bounds__(256)
void context_mma(float* attn)
{
    extern __shared__ char smraw[];
    __nv_bfloat16* Ah = (__nv_bfloat16*)smraw;   // [2][128*40]
    __nv_bfloat16* Al = Ah + 2 * 5120;
    __nv_bfloat16* Bh = Ah + 4 * 5120;           // [2][64*40]
    __nv_bfloat16* Bl = Ah + 4 * 5120 + 2 * 2560;
    __shared__ float sm_m[128], sm_i[128];
    const int t = threadIdx.x, lane = t & 31, wid = t >> 5;
    const int wm = wid >> 1, wn = wid & 1;
    const int gid = lane >> 2, tig = lane & 3;
    const int bh = blockIdx.y, q0 = blockIdx.x * 128;
    const int b = bh >> 4, h = bh & 15;
    float* Am = attn + (size_t)bh * cS * cS;
    const float* Vm = g_V + (size_t)bh * cS * cHD;

    const uint32_t uAh = smem_u32(Ah);
    const uint32_t uAl = uAh + 2 * 5120 * 2;
    const uint32_t uBh = uAh + 4 * 5120 * 2;
    const uint32_t uBl = uAh + (4 * 5120 + 2 * 2560) * 2;
    const uint32_t laneA = ldsmA_off(lane, 80) + (uint32_t)(wm * 32 * 80);
    const uint32_t laneB = ldsmB_off(lane, 80) + (uint32_t)(wn * 32 * 80);

    if (t < 128) {
        float2 rs = g_rowstats[(size_t)bh * cS + q0 + t];
        sm_m[t] = rs.x; sm_i[t] = rs.y;
    }

    float c[2][4][4] = {};
    float4 rA[4], rB[2];

#pragma unroll
    for (int i = 0; i < 4; i++) {
        int idx = t + i * 256, r = idx >> 3, kq = idx & 7;
        rA[i] = *(const float4*)&Am[(size_t)(q0 + r) * cS + kq * 4];
    }
#pragma unroll
    for (int i = 0; i < 2; i++) {
        int idx = t + i * 256, sl = idx >> 4, dq = idx & 15;
        rB[i] = *(const float4*)&Vm[(size_t)sl * 64 + dq * 4];
    }
    __syncthreads();  // sm_m/sm_i visible
#pragma unroll
    for (int i = 0; i < 4; i++) {
        int idx = t + i * 256, r = idx >> 3, kq = idx & 7;
        float mm = sm_m[r], ii = sm_i[r];
        float4 p;
        p.x = __expf(rA[i].x - mm) * ii;
        p.y = __expf(rA[i].y - mm) * ii;
        p.z = __expf(rA[i].z - mm) * ii;
        p.w = __expf(rA[i].w - mm) * ii;
        *(float4*)&Am[(size_t)(q0 + r) * cS + kq * 4] = p;
        uint2 hp, lp;
        split4_pk(p, hp, lp);
        *(uint2*)&Ah[r * 40 + kq * 4] = hp;
        *(uint2*)&Al[r * 40 + kq * 4] = lp;
    }
#pragma unroll
    for (int i = 0; i < 2; i++) {
        int idx = t + i * 256, sl = idx >> 4, dq = idx & 15;
        const float vv[4] = {rB[i].x, rB[i].y, rB[i].z, rB[i].w};
#pragma unroll
        for (int j = 0; j < 4; j++) {
            __nv_bfloat16 hh, ll;
            split1(vv[j], hh, ll);
            Bh[(dq * 4 + j) * 40 + sl] = hh;
            Bl[(dq * 4 + j) * 40 + sl] = ll;
        }
    }
    __syncthreads();

    const int T = 64;
    for (int ch = 0; ch < T; ch++) {
        const int cur = ch & 1;
        if (ch + 1 < T) {
#pragma unroll
            for (int i = 0; i < 4; i++) {
                int idx = t + i * 256, r = idx >> 3, kq = idx & 7;
                rA[i] = *(const float4*)&Am[(size_t)(q0 + r) * cS + (ch + 1) * 32 + kq * 4];
            }
#pragma unroll
            for (int i = 0; i < 2; i++) {
                int idx = t + i * 256, sl = idx >> 4, dq = idx & 15;
                rB[i] = *(const float4*)&Vm[(size_t)((ch + 1) * 32 + sl) * 64 + dq * 4];
            }
        }
        const uint32_t bufA = (uint32_t)cur * 10240;
        const uint32_t bufB = (uint32_t)cur * 5120;
#pragma unroll
        for (int kk = 0; kk < 2; kk++) {
            uint32_t ah[2][4], al[2][4], bh2[4][2], bl2[4][2];
            const uint32_t ko = (uint32_t)kk * 32;
#pragma unroll
            for (int mi = 0; mi < 2; mi++) {
                uint32_t ao = bufA + laneA + (uint32_t)(mi * 16 * 80) + ko;
                ldsm_x4(ah[mi][0], ah[mi][1], ah[mi][2], ah[mi][3], uAh + ao);
                ldsm_x4(al[mi][0], al[mi][1], al[mi][2], al[mi][3], uAl + ao);
            }
#pragma unroll
            for (int p = 0; p < 2; p++) {
                uint32_t bo = bufB + laneB + (uint32_t)(p * 16 * 80) + ko;
                ldsm_x4(bh2[2*p][0], bh2[2*p][1], bh2[2*p+1][0], bh2[2*p+1][1], uBh + bo);
                ldsm_x4(bl2[2*p][0], bl2[2*p][1], bl2[2*p+1][0], bl2[2*p+1][1], uBl + bo);
            }
#pragma unroll
            for (int mi = 0; mi < 2; mi++)
#pragma unroll
                for (int ni = 0; ni < 4; ni++) {
                    mma_bf16(c[mi][ni], al[mi], bh2[ni]);
                    mma_bf16(c[mi][ni], ah[mi], bl2[ni]);
                    mma_bf16(c[mi][ni], ah[mi], bh2[ni]);
                }
        }
        __syncthreads();
        if (ch + 1 < T) {
            __nv_bfloat16* Ahw = Ah + (cur ^ 1) * 5120;
            __nv_bfloat16* Alw = Al + (cur ^ 1) * 5120;
            __nv_bfloat16* Bhw = Bh + (cur ^ 1) * 2560;
            __nv_bfloat16* Blw = Bl + (cur ^ 1) * 2560;
#pragma unroll
            for (int i = 0; i < 4; i++) {
                int idx = t + i * 256, r = idx >> 3, kq = idx & 7;
                float mm = sm_m[r], ii = sm_i[r];
                float4 p;
                p.x = __expf(rA[i].x - mm) * ii;
                p.y = __expf(rA[i].y - mm) * ii;
                p.z = __expf(rA[i].z - mm) * ii;
                p.w = __expf(rA[i].w - mm) * ii;
                *(float4*)&Am[(size_t)(q0 + r) * cS + (ch + 1) * 32 + kq * 4] = p;
                uint2 hp, lp;
                split4_pk(p, hp, lp);
                *(uint2*)&Ahw[r * 40 + kq * 4] = hp;
                *(uint2*)&Alw[r * 40 + kq * 4] = lp;
            }
#pragma unroll
            for (int i = 0; i < 2; i++) {
                int idx = t + i * 256, sl = idx >> 4, dq = idx & 15;
                const float vv[4] = {rB[i].x, rB[i].y, rB[i].z, rB[i].w};
#pragma unroll
                for (int j = 0; j < 4; j++) {
                    __nv_bfloat16 hh, ll;
                    split1(vv[j], hh, ll);
                    Bhw[(dq * 4 + j) * 40 + sl] = hh;
                    Blw[(dq * 4 + j) * 40 + sl] = ll;
                }
            }
            __syncthreads();
        }
    }

#pragma unroll
    for (int mi = 0; mi < 2; mi++)
#pragma unroll
        for (int half = 0; half < 2; half++) {
            int s = q0 + wm * 32 + mi * 16 + gid + half * 8;
#pragma unroll
            for (int ni = 0; ni < 4; ni++) {
                int n = wn * 32 + ni * 8 + tig * 2;
                float2 v;
                v.x = c[mi][ni][half * 2 + 0];
                v.y = c[mi][ni][half * 2 + 1];
                *(float2*)&g_ctx[((size_t)(b * cS + s)) * cHS + h * cHD + n] = v;
            }
        }
}

// ===========================================================================
// Weight transpose + pattern selector (unchanged)
// ===========================================================================
__global__ void transpose_w(const float* __restrict__ W0, const float* __restrict__ W1,
                            const float* __restrict__ W2, const float* __restrict__ W3)
{
    __shared__ float tile[32][33];
    const float* W = blockIdx.z == 0 ? W0 : blockIdx.z == 1 ? W1 : blockIdx.z == 2 ? W2 : W3;
    float* O = g_WT + (size_t)blockIdx.z * cHS * cHS;
    int x = blockIdx.x * 32 + threadIdx.x;
    int y0 = blockIdx.y * 32;
#pragma unroll
    for (int i = 0; i < 4; i++)
        tile[threadIdx.y + i * 8][threadIdx.x] = W[(size_t)(y0 + threadIdx.y + i * 8) * cHS + x];
    __syncthreads();
    int nx = blockIdx.y * 32 + threadIdx.x;
    int ny0 = blockIdx.x * 32;
#pragma unroll
    for (int i = 0; i < 4; i++)
        O[(size_t)(ny0 + threadIdx.y + i * 8) * cHS + nx] = tile[threadIdx.x][threadIdx.y + i * 8];
}

__global__ void qmean_partial(const float* __restrict__ query)
{
    const int b = blockIdx.y, tile = blockIdx.x;
    const int t = threadIdx.x;
    const int r0 = tile * 128;
    float s1 = 0.f, s2 = 0.f;
    for (int r = 0; r < 128; r++) {
        const float* base = query + ((size_t)b * cS + r0 + r) * cHS;
        s1 += base[t];
        s2 += base[t + 512];
    }
    g_qpart[(b * 16 + tile) * cHS + t] = s1;
    g_qpart[(b * 16 + tile) * cHS + t + 512] = s2;
}

__global__ __launch_bounds__(512)
void pattern_kernel(const float* __restrict__ Wp1, const float* __restrict__ bp1,
                    const float* __restrict__ Wp2, const float* __restrict__ bp2,
                    const float* __restrict__ patterns)
{
    const int b = blockIdx.x;
    const int t = threadIdx.x;
    __shared__ float qm[cHS];
    __shared__ float hb[cHS / 2];
    __shared__ float pw[cNP];
    for (int c = t; c < cHS; c += 512) {
        float s = 0.f;
        for (int p = 0; p < 16; p++) s += g_qpart[(b * 16 + p) * cHS + c];
        qm[c] = s * (1.0f / cS);
    }
    __syncthreads();
    {
        float a = bp1[t];
        for (int c = 0; c < cHS; c++) a += qm[c] * Wp1[c * (cHS / 2) + t];
        hb[t] = fmaxf(a, 0.f);
    }
    __syncthreads();
    __shared__ float lg[cNP];
    if (t < cNP) {
        float a = bp2[t];
        for (int j = 0; j < cHS / 2; j++) a += hb[j] * Wp2[j * cNP + t];
        lg[t] = a;
    }
    __syncthreads();
    if (t == 0) {
        float mx = lg[0];
        for (int p = 1; p < cNP; p++) mx = fmaxf(mx, lg[p]);
        float s = 0.f;
        for (int p = 0; p < cNP; p++) { pw[p] = __expf(lg[p] - mx); s += pw[p]; }
        float inv = 1.0f / s;
        for (int p = 0; p < cNP; p++) pw[p] *= inv;
    }
    __syncthreads();
    if (t < cNH) {
        float a = 0.f;
        for (int p = 0; p < cNP; p++) a += pw[p] * patterns[p * cNH + t];
        g_pat[b * cNH + t] = a;
    }
}

// ===========================================================================
// kernel_launch
// ===========================================================================
extern "C" void kernel_launch(void* const* d_in, const int* in_sizes, int n_in,
                              void* d_out, int out_size)
{
    const float* query = (const float*)d_in[0];
    const float* key   = (const float*)d_in[1];
    const float* value = (const float*)d_in[2];
    const int*   mask  = (const int*)d_in[3];
    const float* Wq  = (const float*)d_in[4];  const float* bq  = (const float*)d_in[5];
    const float* Wk  = (const float*)d_in[6];  const float* bk  = (const float*)d_in[7];
    const float* Wv  = (const float*)d_in[8];  const float* bv  = (const float*)d_in[9];
    const float* Wo  = (const float*)d_in[10]; const float* bo  = (const float*)d_in[11];
    const float* Wp1 = (const float*)d_in[12]; const float* bp1 = (const float*)d_in[13];
    const float* Wp2 = (const float*)d_in[14]; const float* bp2 = (const float*)d_in[15];
    const float* patterns = (const float*)d_in[16];
    float* out = (float*)d_out;

    void *pQ, *pK, *pV, *pCtx, *pWT;
    cudaGetSymbolAddress(&pQ, g_Q);
    cudaGetSymbolAddress(&pK, g_K);
    cudaGetSymbolAddress(&pV, g_V);
    cudaGetSymbolAddress(&pCtx, g_ctx);
    cudaGetSymbolAddress(&pWT, g_WT);
    const float* WT = (const float*)pWT;

    float* attn;
    if ((long)out_size >= OUT_ELEMS + ATTN_ELEMS) {
        attn = out + OUT_ELEMS;
    } else {
        void* pa;
        cudaGetSymbolAddress(&pa, g_attn_fallback);
        attn = (float*)pa;
    }

    const int SM_GEMM   = 8 * 5120 * 2;               // 81920
    const int SM_SCORES = 2 * 9216 * 2;               // 36864
    const int SM_CTX    = (4 * 5120 + 4 * 2560) * 2;  // 61440
    cudaFuncSetAttribute(gemm_bf<1>,  cudaFuncAttributeMaxDynamicSharedMemorySize, SM_GEMM);
    cudaFuncSetAttribute(gemm_bf<0>,  cudaFuncAttributeMaxDynamicSharedMemorySize, SM_GEMM);
    cudaFuncSetAttribute(scores_mma,  cudaFuncAttributeMaxDynamicSharedMemorySize, SM_SCORES);
    cudaFuncSetAttribute(context_mma, cudaFuncAttributeMaxDynamicSharedMemorySize, SM_CTX);

    // 1. pattern selector
    qmean_partial<<<dim3(16, cB), 512>>>(query);
    pattern_kernel<<<cB, 512>>>(Wp1, bp1, Wp2, bp2, patterns);

    // 2. transpose weights
    transpose_w<<<dim3(32, 32, 4), dim3(32, 8)>>>(Wq, Wk, Wv, Wo);

    // 3. merged QKV projection -> [B,NH,S,HD] (Q/K 2-term, V 3-term)
    dim3 gProj(cHS / 128, (cB * cS) / 128, 3);
    gemm_bf<1><<<gProj, 256, SM_GEMM>>>(query, key, value, WT, bq, bk, bv,
                                        (float*)pQ, (float*)pK, (float*)pV);

    // 4. raw scores + LSE partials (pure bf16)
    dim3 gScores(cS / 128, cS / 128, cB * cNH);
    scores_mma<<<gScores, 256, SM_SCORES>>>(mask, attn);

    // 5. merge row stats
    merge_stats<<<(cB * cNH * cS) / 256, 256>>>();

    // 6. fused softmax + context (full 3-term)
    dim3 gCtx(cS / 128, cB * cNH);
    context_mma<<<gCtx, 256, SM_CTX>>>(attn);

    // 7. output projection (full 3-term)
    dim3 gOut(cHS / 128, (cB * cS) / 128, 1);
    gemm_bf<0><<<gOut, 256, SM_GEMM>>>((const float*)pCtx, nullptr, nullptr,
                                       WT + 3L * cHS * cHS, bo, nullptr, nullptr,
                                       out, nullptr, nullptr);
}